// round 10
// baseline (speedup 1.0000x reference)
#include <cuda_runtime.h>
#include <math.h>
#include <stdint.h>

// Problem dims
#define N_TOK 2048
#define CDIM  1024
#define RH    256
#define NE    8
#define IDIM  4096
#define SEG   2048
#define R_EXP (NE*SEG)          // 16384
#define R_TOT (R_EXP + N_TOK)   // 18432
#define MT_TOT (R_TOT/128)      // 144 row tiles
#define KC 32                   // K chunk

// SMEM layout (bytes). Per buffer: A_hi[128][40]bf16, A_lo, B_hi[32][136]bf16, B_lo
#define OFF_TOK  64
#define OFF_AHI  1024
#define A_ARR    10240                  // 128*80
#define OFF_ALO  (OFF_AHI + A_ARR)      // 11264
#define OFF_BHI  (OFF_ALO + A_ARR)      // 21504
#define B_ARR    8704                   // 32*272
#define OFF_BLO  (OFF_BHI + B_ARR)      // 30208
#define SBUF     (2*A_ARR + 2*B_ARR)    // 37888 (one buffer)
#define SMEM_TOTAL (1024 + 2*SBUF)      // 76800

// Scratch
__device__ float g_y1p[(size_t)8 * N_TOK * RH];   // router split-K partials
__device__ float g_h [(size_t)R_TOT * IDIM];      // silu(x@W1+b1)
__device__ float g_eo[(size_t)R_TOT * CDIM];      // h@W2+b2 per row
__device__ int   g_cnt[NE];
__device__ int   g_ptok[R_EXP];
__device__ int   g_tpos[N_TOK * 2];
__device__ float g_tw  [N_TOK * 2];

// ---------------------------------------------------------------------------
// helpers (all legal on base sm_103 target)
// ---------------------------------------------------------------------------
__device__ __forceinline__ void mma_bf16(float* d, const uint32_t* a, const uint32_t* b) {
    asm volatile(
        "mma.sync.aligned.m16n8k16.row.col.f32.bf16.bf16.f32 "
        "{%0,%1,%2,%3},{%4,%5,%6,%7},{%8,%9},{%0,%1,%2,%3};\n"
        : "+f"(d[0]), "+f"(d[1]), "+f"(d[2]), "+f"(d[3])
        : "r"(a[0]), "r"(a[1]), "r"(a[2]), "r"(a[3]), "r"(b[0]), "r"(b[1]));
}
#define LDMX4(r0,r1,r2,r3,addr) \
    asm volatile("ldmatrix.sync.aligned.m8n8.x4.shared.b16 {%0,%1,%2,%3}, [%4];" \
        : "=r"(r0),"=r"(r1),"=r"(r2),"=r"(r3) : "r"(addr))
#define LDMX2T(r0,r1,addr) \
    asm volatile("ldmatrix.sync.aligned.m8n8.x2.trans.shared.b16 {%0,%1}, [%2];" \
        : "=r"(r0),"=r"(r1) : "r"(addr))

// Split (v0, v1) fp32 pair into packed bf16x2 hi word + bf16x2 lo-residual word.
// Low half of each word = v0 (lower k index).
#define SPLIT2(hw, lw, v0, v1) do { \
    asm("cvt.rn.bf16x2.f32 %0, %1, %2;" : "=r"(hw) : "f"(v1), "f"(v0)); \
    float _h0 = __uint_as_float((hw) << 16); \
    float _h1 = __uint_as_float((hw) & 0xffff0000u); \
    float _r0 = (v0) - _h0, _r1 = (v1) - _h1; \
    asm("cvt.rn.bf16x2.f32 %0, %1, %2;" : "=r"(lw) : "f"(_r1), "f"(_r0)); \
} while (0)

__device__ __forceinline__ uint32_t smem_u32(const void* p) {
    uint32_t a;
    asm("{ .reg .u64 t; cvta.to.shared.u64 t, %1; cvt.u32.u64 %0, t; }"
        : "=r"(a) : "l"(p));
    return a;
}

// ---------------------------------------------------------------------------
// 0) init counters
// ---------------------------------------------------------------------------
__global__ void init_kernel() {
    if (threadIdx.x < NE) g_cnt[threadIdx.x] = 0;
}

// ---------------------------------------------------------------------------
// 1) router GEMM split-K=8 (deterministic partials): y1p[s] = x[:,ks] @ rw1[ks,:]
// ---------------------------------------------------------------------------
__global__ void __launch_bounds__(256, 2)
router_gemm(const float* __restrict__ x, const float* __restrict__ rw1) {
    __shared__ float As[8][128];
    __shared__ float Bs[8][128];
    const int tid = threadIdx.x;
    const int m0 = blockIdx.y * 128;
    const int n0 = blockIdx.x * 128;
    const int ks = blockIdx.z * 128;

    const int ar = tid >> 1, kh = (tid & 1) * 4;
    const int kb = tid >> 5, bn = (tid & 31) * 4;
    const float* arow = x + (size_t)(m0 + ar) * CDIM + ks;
    const float* bptr = rw1 + (size_t)(ks + kb) * RH + n0 + bn;
    const int tm = (tid >> 4) * 8, tn = (tid & 15) * 8;

    float acc[8][8];
#pragma unroll
    for (int i = 0; i < 8; i++)
#pragma unroll
        for (int j = 0; j < 8; j++) acc[i][j] = 0.0f;

    for (int k0 = 0; k0 < 128; k0 += 8) {
        float4 av = *(const float4*)(arow + k0 + kh);
        As[kh + 0][ar] = av.x; As[kh + 1][ar] = av.y;
        As[kh + 2][ar] = av.z; As[kh + 3][ar] = av.w;
        *(float4*)&Bs[kb][bn] = *(const float4*)(bptr + (size_t)k0 * RH);
        __syncthreads();
#pragma unroll
        for (int kk = 0; kk < 8; kk++) {
            float a[8], b[8];
#pragma unroll
            for (int i = 0; i < 8; i++) a[i] = As[kk][tm + i];
#pragma unroll
            for (int j = 0; j < 8; j++) b[j] = Bs[kk][tn + j];
#pragma unroll
            for (int i = 0; i < 8; i++)
#pragma unroll
                for (int j = 0; j < 8; j++) acc[i][j] += a[i] * b[j];
        }
        __syncthreads();
    }
#pragma unroll
    for (int i = 0; i < 8; i++) {
        float* dst = g_y1p + ((size_t)blockIdx.z * N_TOK + m0 + tm + i) * RH + n0 + tn;
#pragma unroll
        for (int j = 0; j < 8; j++) dst[j] = acc[i][j];
    }
}

// ---------------------------------------------------------------------------
// 2) routing: sum partials, +rb1, relu, @rw2+rb2, softmax, top2, scatter
// ---------------------------------------------------------------------------
__global__ void route_kernel(const float* __restrict__ rw2,
                             const float* __restrict__ rb2,
                             const float* __restrict__ rb1) {
    __shared__ float s_w[RH * NE];
    __shared__ float s_b[NE];
    __shared__ float s_b1[RH];
    const int tid = threadIdx.x;
    for (int i = tid; i < RH * NE; i += 256) s_w[i] = rw2[i];
    if (tid < NE) s_b[tid] = rb2[tid];
    if (tid < RH) s_b1[tid] = rb1[tid];
    __syncthreads();

    const int n = blockIdx.x * 256 + tid;

    float acc[NE];
#pragma unroll
    for (int e = 0; e < NE; e++) acc[e] = s_b[e];
    for (int c = 0; c < RH; c++) {
        float vv = 0.0f;
#pragma unroll
        for (int s = 0; s < 8; s++)
            vv += g_y1p[((size_t)s * N_TOK + n) * RH + c];
        float v = fmaxf(vv + s_b1[c], 0.0f);
#pragma unroll
        for (int e = 0; e < NE; e++) acc[e] += v * s_w[c * NE + e];
    }

    float m = acc[0];
#pragma unroll
    for (int e = 1; e < NE; e++) m = fmaxf(m, acc[e]);
    float s = 0.0f, g[NE];
#pragma unroll
    for (int e = 0; e < NE; e++) { g[e] = expf(acc[e] - m); s += g[e]; }
    float inv = 1.0f / s;
#pragma unroll
    for (int e = 0; e < NE; e++) g[e] *= inv;

    int i1 = 0; float g1 = g[0];
#pragma unroll
    for (int e = 1; e < NE; e++) if (g[e] > g1) { g1 = g[e]; i1 = e; }
    int i2 = -1; float g2 = -1.0f;
#pragma unroll
    for (int e = 0; e < NE; e++)
        if (e != i1 && g[e] > g2) { g2 = g[e]; i2 = e; }

    float t  = expf((g2 - g1) * 0.5f);
    float d  = 1.0f / (1.0f + t);
    float w1 = d, w2 = t * d;

    int p1 = atomicAdd(&g_cnt[i1], 1);
    g_ptok[i1 * SEG + p1] = n;
    g_tpos[n * 2] = i1 * SEG + p1; g_tw[n * 2] = w1;
    int p2 = atomicAdd(&g_cnt[i2], 1);
    g_ptok[i2 * SEG + p2] = n;
    g_tpos[n * 2 + 1] = i2 * SEG + p2; g_tw[n * 2 + 1] = w2;
}

// ---------------------------------------------------------------------------
// bf16x3 HMMA mainloop (R6-validated, verbatim).
// A[128 x KC] from aptr (per-thread row base), B[128n x KC] from W (k-major,
// ld = LDB). SMEM: A as [m][k] bf16 hi/lo (80B rows), B as [k][n] bf16 hi/lo
// (272B rows, ldmatrix.trans). Double-buffered, 1 sync/chunk, LDG prefetch.
// ---------------------------------------------------------------------------
#define GEMM_MAINLOOP(LDB, NCH)                                                \
    const int wid = tid >> 5, lane = tid & 31;                                 \
    const int wm = wid & 3, wn = wid >> 2;                                     \
    const int g = lane >> 2, tt = lane & 3;                                    \
    const int akh = (tid & 1) * 16;                                            \
    const int bkr = tid >> 3, bng = (tid & 7) * 16;                            \
    char* a_st = smem + OFF_AHI + (tid >> 1) * 80 + akh * 2;                   \
    char* b_st = smem + OFF_BHI + bkr * 272 + bng * 2;                         \
    const float* bsrc0 = W + (size_t)bkr * (LDB) + n0 + bng;                   \
    const uint32_t a_lm = smem_base + OFF_AHI +                                \
        (uint32_t)((wm * 32 + (lane & 15)) * 80 + (lane >> 4) * 16);           \
    const uint32_t b_lm = smem_base + OFF_BHI +                                \
        (uint32_t)((lane & 15) * 272 + wn * 128);                              \
    float acc[2][8][4];                                                        \
    _Pragma("unroll")                                                          \
    for (int i = 0; i < 2; i++)                                                \
        _Pragma("unroll")                                                      \
        for (int j = 0; j < 8; j++)                                            \
            _Pragma("unroll")                                                  \
            for (int q = 0; q < 4; q++) acc[i][j][q] = 0.0f;                   \
    float4 pa[4], pb[4];                                                       \
    _Pragma("unroll")                                                          \
    for (int m = 0; m < 4; m++) {                                              \
        pa[m] = *(const float4*)(aptr + akh + m * 4);                          \
        pb[m] = *(const float4*)(bsrc0 + m * 4);                               \
    }                                                                          \
    for (int c = 0; c < (NCH); c++) {                                          \
        const uint32_t boff = (uint32_t)(c & 1) * SBUF;                        \
        uint32_t hw[8], lw[8];                                                 \
        SPLIT2(hw[0], lw[0], pa[0].x, pa[0].y);                                \
        SPLIT2(hw[1], lw[1], pa[0].z, pa[0].w);                                \
        SPLIT2(hw[2], lw[2], pa[1].x, pa[1].y);                                \
        SPLIT2(hw[3], lw[3], pa[1].z, pa[1].w);                                \
        SPLIT2(hw[4], lw[4], pa[2].x, pa[2].y);                                \
        SPLIT2(hw[5], lw[5], pa[2].z, pa[2].w);                                \
        SPLIT2(hw[6], lw[6], pa[3].x, pa[3].y);                                \
        SPLIT2(hw[7], lw[7], pa[3].z, pa[3].w);                                \
        *(uint4*)(a_st + boff)      = make_uint4(hw[0],hw[1],hw[2],hw[3]);     \
        *(uint4*)(a_st + boff + 16) = make_uint4(hw[4],hw[5],hw[6],hw[7]);     \
        *(uint4*)(a_st + boff + A_ARR)      = make_uint4(lw[0],lw[1],lw[2],lw[3]); \
        *(uint4*)(a_st + boff + A_ARR + 16) = make_uint4(lw[4],lw[5],lw[6],lw[7]); \
        SPLIT2(hw[0], lw[0], pb[0].x, pb[0].y);                                \
        SPLIT2(hw[1], lw[1], pb[0].z, pb[0].w);                                \
        SPLIT2(hw[2], lw[2], pb[1].x, pb[1].y);                                \
        SPLIT2(hw[3], lw[3], pb[1].z, pb[1].w);                                \
        SPLIT2(hw[4], lw[4], pb[2].x, pb[2].y);                                \
        SPLIT2(hw[5], lw[5], pb[2].z, pb[2].w);                                \
        SPLIT2(hw[6], lw[6], pb[3].x, pb[3].y);                                \
        SPLIT2(hw[7], lw[7], pb[3].z, pb[3].w);                                \
        *(uint4*)(b_st + boff)      = make_uint4(hw[0],hw[1],hw[2],hw[3]);     \
        *(uint4*)(b_st + boff + 16) = make_uint4(hw[4],hw[5],hw[6],hw[7]);     \
        *(uint4*)(b_st + boff + B_ARR)      = make_uint4(lw[0],lw[1],lw[2],lw[3]); \
        *(uint4*)(b_st + boff + B_ARR + 16) = make_uint4(lw[4],lw[5],lw[6],lw[7]); \
        __syncthreads();                                                       \
        if (c + 1 < (NCH)) {                                                   \
            const float* asrc = aptr + (c + 1) * KC + akh;                     \
            const float* bsrc = bsrc0 + (size_t)(c + 1) * KC * (LDB);          \
            _Pragma("unroll")                                                  \
            for (int m = 0; m < 4; m++) {                                      \
                pa[m] = *(const float4*)(asrc + m * 4);                        \
                pb[m] = *(const float4*)(bsrc + m * 4);                        \
            }                                                                  \
        }                                                                      \
        _Pragma("unroll")                                                      \
        for (int slab = 0; slab < 2; slab++) {                                 \
            uint32_t ah[2][4], al[2][4];                                       \
            _Pragma("unroll")                                                  \
            for (int i = 0; i < 2; i++) {                                      \
                uint32_t aa = a_lm + boff + (uint32_t)(i * 1280 + slab * 32);  \
                LDMX4(ah[i][0], ah[i][1], ah[i][2], ah[i][3], aa);             \
                LDMX4(al[i][0], al[i][1], al[i][2], al[i][3], aa + A_ARR);     \
            }                                                                  \
            _Pragma("unroll")                                                  \
            for (int j = 0; j < 8; j++) {                                      \
                uint32_t bh[2], bl[2];                                         \
                uint32_t ba = b_lm + boff + (uint32_t)(slab * 4352 + j * 16);  \
                LDMX2T(bh[0], bh[1], ba);                                      \
                LDMX2T(bl[0], bl[1], ba + B_ARR);                              \
                _Pragma("unroll")                                              \
                for (int i = 0; i < 2; i++) {                                  \
                    mma_bf16(acc[i][j], ah[i], bh);                            \
                    mma_bf16(acc[i][j], al[i], bh);                            \
                    mma_bf16(acc[i][j], ah[i], bl);                            \
                }                                                              \
            }                                                                  \
        }                                                                      \
    }

// ---------------------------------------------------------------------------
// 3) grouped GEMM1: h = silu(gather(x) @ W1 + b1). grid (IDIM/128=32, 144)
// ---------------------------------------------------------------------------
__global__ void __launch_bounds__(256)
gemm1_k(const float* __restrict__ x,  const float* __restrict__ ew1,
        const float* __restrict__ eb1, const float* __restrict__ sw1,
        const float* __restrict__ sb1) {
    extern __shared__ char smem[];
    const int t = blockIdx.y, n0 = blockIdx.x * 128, tid = threadIdx.x;
    int* s_tok = (int*)(smem + OFF_TOK);

    const float* W; const float* bias;
    if (t < 128) {
        int e = t >> 4;
        int cnt = g_cnt[e];
        int lr0 = (t & 15) * 128;
        if (lr0 >= cnt) return;
        W = ew1 + (size_t)e * CDIM * IDIM;
        bias = eb1 + (size_t)e * IDIM;
        if (tid < 128) {
            int lr = lr0 + tid;
            s_tok[tid] = (lr < cnt) ? g_ptok[e * SEG + lr] : 0;
        }
    } else {
        W = sw1; bias = sb1;
        if (tid < 128) s_tok[tid] = (t - 128) * 128 + tid;
    }
    __syncthreads();

    uint32_t smem_base = smem_u32(smem);
    const float* aptr = x + (size_t)s_tok[tid >> 1] * CDIM;

    GEMM_MAINLOOP(IDIM, CDIM / KC)

#pragma unroll
    for (int i = 0; i < 2; i++)
#pragma unroll
        for (int j = 0; j < 8; j++) {
            const int row0 = t * 128 + wm * 32 + i * 16 + g;
            const int col = n0 + wn * 64 + j * 8 + 2 * tt;
            float b0 = bias[col], b1 = bias[col + 1];
            float v0 = acc[i][j][0] + b0, v1 = acc[i][j][1] + b1;
            float v2 = acc[i][j][2] + b0, v3 = acc[i][j][3] + b1;
            float2 lo, hi;
            lo.x = v0 / (1.0f + __expf(-v0)); lo.y = v1 / (1.0f + __expf(-v1));
            hi.x = v2 / (1.0f + __expf(-v2)); hi.y = v3 / (1.0f + __expf(-v3));
            *(float2*)(g_h + (size_t)row0 * IDIM + col) = lo;
            *(float2*)(g_h + (size_t)(row0 + 8) * IDIM + col) = hi;
        }
}

// ---------------------------------------------------------------------------
// 4) grouped GEMM2: eo = h @ W2 + b2. grid (CDIM/128=8, 144). K=4096
// ---------------------------------------------------------------------------
__global__ void __launch_bounds__(256)
gemm2_k(const float* __restrict__ ew2, const float* __restrict__ eb2,
        const float* __restrict__ sw2, const float* __restrict__ sb2) {
    extern __shared__ char smem[];
    const int t = blockIdx.y, n0 = blockIdx.x * 128, tid = threadIdx.x;

    const float* W; const float* bias;
    if (t < 128) {
        int e = t >> 4;
        if ((t & 15) * 128 >= g_cnt[e]) return;
        W = ew2 + (size_t)e * IDIM * CDIM;
        bias = eb2 + (size_t)e * CDIM;
    } else {
        W = sw2; bias = sb2;
    }
    __syncthreads();

    uint32_t smem_base = smem_u32(smem);
    const float* aptr = g_h + (size_t)(t * 128 + (tid >> 1)) * IDIM;

    GEMM_MAINLOOP(CDIM, IDIM / KC)

#pragma unroll
    for (int i = 0; i < 2; i++)
#pragma unroll
        for (int j = 0; j < 8; j++) {
            const int row0 = t * 128 + wm * 32 + i * 16 + g;
            const int col = n0 + wn * 64 + j * 8 + 2 * tt;
            float b0 = bias[col], b1 = bias[col + 1];
            float2 lo, hi;
            lo.x = acc[i][j][0] + b0; lo.y = acc[i][j][1] + b1;
            hi.x = acc[i][j][2] + b0; hi.y = acc[i][j][3] + b1;
            *(float2*)(g_eo + (size_t)row0 * CDIM + col) = lo;
            *(float2*)(g_eo + (size_t)(row0 + 8) * CDIM + col) = hi;
        }
}

// ---------------------------------------------------------------------------
// 5) combine: out[n] = eo[shared_n] + w0*eo[pos0] + w1*eo[pos1]
// ---------------------------------------------------------------------------
__global__ void combine_kernel(float* __restrict__ out) {
    int gid = blockIdx.x * 256 + threadIdx.x;
    int n = gid >> 8, c4 = gid & 255;
    const float4* eo = (const float4*)g_eo;
    float4 o = eo[(size_t)(R_EXP + n) * (CDIM / 4) + c4];
    int   p0 = g_tpos[n * 2],     p1 = g_tpos[n * 2 + 1];
    float w0 = g_tw[n * 2],       w1 = g_tw[n * 2 + 1];
    float4 a = eo[(size_t)p0 * (CDIM / 4) + c4];
    float4 b = eo[(size_t)p1 * (CDIM / 4) + c4];
    o.x += w0 * a.x + w1 * b.x;
    o.y += w0 * a.y + w1 * b.y;
    o.z += w0 * a.z + w1 * b.z;
    o.w += w0 * a.w + w1 * b.w;
    ((float4*)out)[gid] = o;
}

// ---------------------------------------------------------------------------
extern "C" void kernel_launch(void* const* d_in, const int* in_sizes, int n_in,
                              void* d_out, int out_size) {
    const float* x   = (const float*)d_in[0];
    const float* rw1 = (const float*)d_in[1];
    const float* rb1 = (const float*)d_in[2];
    const float* rw2 = (const float*)d_in[3];
    const float* rb2 = (const float*)d_in[4];
    const float* ew1 = (const float*)d_in[5];
    const float* eb1 = (const float*)d_in[6];
    const float* ew2 = (const float*)d_in[7];
    const float* eb2 = (const float*)d_in[8];
    const float* sw1 = (const float*)d_in[9];
    const float* sb1 = (const float*)d_in[10];
    const float* sw2 = (const float*)d_in[11];
    const float* sb2 = (const float*)d_in[12];
    float* out = (float*)d_out;

    static bool attr_done = false;
    if (!attr_done) {
        cudaFuncSetAttribute(gemm1_k, cudaFuncAttributeMaxDynamicSharedMemorySize, SMEM_TOTAL);
        cudaFuncSetAttribute(gemm2_k, cudaFuncAttributeMaxDynamicSharedMemorySize, SMEM_TOTAL);
        attr_done = true;
    }

    init_kernel<<<1, 32>>>();
    router_gemm<<<dim3(2, 16, 8), 256>>>(x, rw1);
    route_kernel<<<8, 256>>>(rw2, rb2, rb1);
    gemm1_k<<<dim3(IDIM / 128, MT_TOT), 256, SMEM_TOTAL>>>(x, ew1, eb1, sw1, sb1);
    gemm2_k<<<dim3(CDIM / 128, MT_TOT), 256, SMEM_TOTAL>>>(ew2, eb2, sw2, sb2);
    combine_kernel<<<N_TOK * CDIM / 4 / 256, 256>>>(out);
}

// round 11
// speedup vs baseline: 1.0776x; 1.0776x over previous
#include <cuda_runtime.h>
#include <math.h>
#include <stdint.h>

// Problem dims
#define N_TOK 2048
#define CDIM  1024
#define RH    256
#define NE    8
#define IDIM  4096
#define SEG   2048
#define R_EXP (NE*SEG)          // 16384
#define R_TOT (R_EXP + N_TOK)   // 18432
#define MT_TOT (R_TOT/128)      // 144 row tiles
#define KC 32                   // K chunk

// SMEM layout (bytes). Per buffer: A_hi[128][40]bf16, A_lo, B_hi[32][136]bf16, B_lo
#define OFF_TOK  64
#define OFF_AHI  1024
#define A_ARR    10240                  // 128*80
#define OFF_ALO  (OFF_AHI + A_ARR)      // 11264
#define OFF_BHI  (OFF_ALO + A_ARR)      // 21504
#define B_ARR    8704                   // 32*272
#define OFF_BLO  (OFF_BHI + B_ARR)      // 30208
#define SBUF     (2*A_ARR + 2*B_ARR)    // 37888 (one buffer)
#define SMEM_TOTAL (1024 + 2*SBUF)      // 76800

// Scratch
__device__ float g_y1[N_TOK * RH];                // router hidden (relu'd)
__device__ float g_h [(size_t)R_TOT * IDIM];      // silu(x@W1+b1)
__device__ float g_eo[(size_t)R_TOT * CDIM];      // h@W2+b2 per row
__device__ int   g_cnt[NE];
__device__ int   g_ptok[R_EXP];
__device__ int   g_tpos[N_TOK * 2];
__device__ float g_tw  [N_TOK * 2];

// ---------------------------------------------------------------------------
// helpers (all legal on base sm_103 target)
// ---------------------------------------------------------------------------
__device__ __forceinline__ void mma_bf16(float* d, const uint32_t* a, const uint32_t* b) {
    asm volatile(
        "mma.sync.aligned.m16n8k16.row.col.f32.bf16.bf16.f32 "
        "{%0,%1,%2,%3},{%4,%5,%6,%7},{%8,%9},{%0,%1,%2,%3};\n"
        : "+f"(d[0]), "+f"(d[1]), "+f"(d[2]), "+f"(d[3])
        : "r"(a[0]), "r"(a[1]), "r"(a[2]), "r"(a[3]), "r"(b[0]), "r"(b[1]));
}
#define LDMX4(r0,r1,r2,r3,addr) \
    asm volatile("ldmatrix.sync.aligned.m8n8.x4.shared.b16 {%0,%1,%2,%3}, [%4];" \
        : "=r"(r0),"=r"(r1),"=r"(r2),"=r"(r3) : "r"(addr))
#define LDMX4T(r0,r1,r2,r3,addr) \
    asm volatile("ldmatrix.sync.aligned.m8n8.x4.trans.shared.b16 {%0,%1,%2,%3}, [%4];" \
        : "=r"(r0),"=r"(r1),"=r"(r2),"=r"(r3) : "r"(addr))

// Split (v0, v1) fp32 pair into packed bf16x2 hi word + bf16x2 lo-residual word.
// Low half of each word = v0 (lower k index).
#define SPLIT2(hw, lw, v0, v1) do { \
    asm("cvt.rn.bf16x2.f32 %0, %1, %2;" : "=r"(hw) : "f"(v1), "f"(v0)); \
    float _h0 = __uint_as_float((hw) << 16); \
    float _h1 = __uint_as_float((hw) & 0xffff0000u); \
    float _r0 = (v0) - _h0, _r1 = (v1) - _h1; \
    asm("cvt.rn.bf16x2.f32 %0, %1, %2;" : "=r"(lw) : "f"(_r1), "f"(_r0)); \
} while (0)

__device__ __forceinline__ uint32_t smem_u32(const void* p) {
    uint32_t a;
    asm("{ .reg .u64 t; cvta.to.shared.u64 t, %1; cvt.u32.u64 %0, t; }"
        : "=r"(a) : "l"(p));
    return a;
}

// ---------------------------------------------------------------------------
// 0) init counters
// ---------------------------------------------------------------------------
__global__ void init_kernel() {
    if (threadIdx.x < NE) g_cnt[threadIdx.x] = 0;
}

// ---------------------------------------------------------------------------
// 1) router GEMM1 (fp32 SIMT, R6-validated): y1 = relu(x @ rw1 + rb1)
// ---------------------------------------------------------------------------
__global__ void __launch_bounds__(256, 2)
router_gemm(const float* __restrict__ x,
            const float* __restrict__ rw1,
            const float* __restrict__ rb1) {
    __shared__ float As[8][128];
    __shared__ float Bs[8][128];
    const int tid = threadIdx.x;
    const int m0 = blockIdx.y * 128;
    const int n0 = blockIdx.x * 128;

    const int ar = tid >> 1, kh = (tid & 1) * 4;
    const int kb = tid >> 5, bn = (tid & 31) * 4;
    const float* arow = x + (size_t)(m0 + ar) * CDIM;
    const float* bptr = rw1 + (size_t)kb * RH + n0 + bn;
    const int tm = (tid >> 4) * 8, tn = (tid & 15) * 8;

    float acc[8][8];
#pragma unroll
    for (int i = 0; i < 8; i++)
#pragma unroll
        for (int j = 0; j < 8; j++) acc[i][j] = 0.0f;

    for (int k0 = 0; k0 < CDIM; k0 += 8) {
        float4 av = *(const float4*)(arow + k0 + kh);
        As[kh + 0][ar] = av.x; As[kh + 1][ar] = av.y;
        As[kh + 2][ar] = av.z; As[kh + 3][ar] = av.w;
        *(float4*)&Bs[kb][bn] = *(const float4*)(bptr + (size_t)k0 * RH);
        __syncthreads();
#pragma unroll
        for (int kk = 0; kk < 8; kk++) {
            float a[8], b[8];
#pragma unroll
            for (int i = 0; i < 8; i++) a[i] = As[kk][tm + i];
#pragma unroll
            for (int j = 0; j < 8; j++) b[j] = Bs[kk][tn + j];
#pragma unroll
            for (int i = 0; i < 8; i++)
#pragma unroll
                for (int j = 0; j < 8; j++) acc[i][j] += a[i] * b[j];
        }
        __syncthreads();
    }

    float bb[8];
#pragma unroll
    for (int j = 0; j < 8; j++) bb[j] = rb1[n0 + tn + j];
#pragma unroll
    for (int i = 0; i < 8; i++) {
        float* yrow = g_y1 + (size_t)(m0 + tm + i) * RH + n0 + tn;
#pragma unroll
        for (int j = 0; j < 8; j++) {
            float v = acc[i][j] + bb[j];
            yrow[j] = v > 0.0f ? v : 0.0f;
        }
    }
}

// ---------------------------------------------------------------------------
// 2) routing (R6-validated): logits -> softmax -> top2 -> scatter + positions
// ---------------------------------------------------------------------------
__global__ void route_kernel(const float* __restrict__ rw2,
                             const float* __restrict__ rb2) {
    __shared__ float s_w[RH * NE];
    __shared__ float s_b[NE];
    const int tid = threadIdx.x;
    for (int i = tid; i < RH * NE; i += 256) s_w[i] = rw2[i];
    if (tid < NE) s_b[tid] = rb2[tid];
    __syncthreads();

    const int n = blockIdx.x * 256 + tid;
    const float* y = g_y1 + (size_t)n * RH;

    float acc[NE];
#pragma unroll
    for (int e = 0; e < NE; e++) acc[e] = s_b[e];
    for (int c = 0; c < RH; c++) {
        float v = y[c];
#pragma unroll
        for (int e = 0; e < NE; e++) acc[e] += v * s_w[c * NE + e];
    }

    float m = acc[0];
#pragma unroll
    for (int e = 1; e < NE; e++) m = fmaxf(m, acc[e]);
    float s = 0.0f, g[NE];
#pragma unroll
    for (int e = 0; e < NE; e++) { g[e] = expf(acc[e] - m); s += g[e]; }
    float inv = 1.0f / s;
#pragma unroll
    for (int e = 0; e < NE; e++) g[e] *= inv;

    int i1 = 0; float g1 = g[0];
#pragma unroll
    for (int e = 1; e < NE; e++) if (g[e] > g1) { g1 = g[e]; i1 = e; }
    int i2 = -1; float g2 = -1.0f;
#pragma unroll
    for (int e = 0; e < NE; e++)
        if (e != i1 && g[e] > g2) { g2 = g[e]; i2 = e; }

    float t  = expf((g2 - g1) * 0.5f);
    float d  = 1.0f / (1.0f + t);
    float w1 = d, w2 = t * d;

    int p1 = atomicAdd(&g_cnt[i1], 1);
    g_ptok[i1 * SEG + p1] = n;
    g_tpos[n * 2] = i1 * SEG + p1; g_tw[n * 2] = w1;
    int p2 = atomicAdd(&g_cnt[i2], 1);
    g_ptok[i2 * SEG + p2] = n;
    g_tpos[n * 2 + 1] = i2 * SEG + p2; g_tw[n * 2 + 1] = w2;
}

// ---------------------------------------------------------------------------
// bf16x3 HMMA mainloop (R6 core; B fragments now via paired ldmatrix.x4.trans).
// A[128 x KC] from aptr (per-thread row base), B[128n x KC] from W (k-major,
// ld = LDB). SMEM: A as [m][k] bf16 hi/lo (80B rows), B as [k][n] bf16 hi/lo
// (272B rows). Double-buffered, 1 sync/chunk, LDG prefetch.
// ---------------------------------------------------------------------------
#define GEMM_MAINLOOP(LDB, NCH)                                                \
    const int wid = tid >> 5, lane = tid & 31;                                 \
    const int wm = wid & 3, wn = wid >> 2;                                     \
    const int g = lane >> 2, tt = lane & 3;                                    \
    const int akh = (tid & 1) * 16;                                            \
    const int bkr = tid >> 3, bng = (tid & 7) * 16;                            \
    char* a_st = smem + OFF_AHI + (tid >> 1) * 80 + akh * 2;                   \
    char* b_st = smem + OFF_BHI + bkr * 272 + bng * 2;                         \
    const float* bsrc0 = W + (size_t)bkr * (LDB) + n0 + bng;                   \
    const uint32_t a_lm = smem_base + OFF_AHI +                                \
        (uint32_t)((wm * 32 + (lane & 15)) * 80 + (lane >> 4) * 16);           \
    const uint32_t b_lm = smem_base + OFF_BHI +                                \
        (uint32_t)(((lane & 7) + ((lane >> 3) & 1) * 8) * 272                  \
                   + (lane >> 4) * 16 + wn * 128);                             \
    float acc[2][8][4];                                                        \
    _Pragma("unroll")                                                          \
    for (int i = 0; i < 2; i++)                                                \
        _Pragma("unroll")                                                      \
        for (int j = 0; j < 8; j++)                                            \
            _Pragma("unroll")                                                  \
            for (int q = 0; q < 4; q++) acc[i][j][q] = 0.0f;                   \
    float4 pa[4], pb[4];                                                       \
    _Pragma("unroll")                                                          \
    for (int m = 0; m < 4; m++) {                                              \
        pa[m] = *(const float4*)(aptr + akh + m * 4);                          \
        pb[m] = *(const float4*)(bsrc0 + m * 4);                               \
    }                                                                          \
    for (int c = 0; c < (NCH); c++) {                                          \
        const uint32_t boff = (uint32_t)(c & 1) * SBUF;                        \
        uint32_t hw[8], lw[8];                                                 \
        SPLIT2(hw[0], lw[0], pa[0].x, pa[0].y);                                \
        SPLIT2(hw[1], lw[1], pa[0].z, pa[0].w);                                \
        SPLIT2(hw[2], lw[2], pa[1].x, pa[1].y);                                \
        SPLIT2(hw[3], lw[3], pa[1].z, pa[1].w);                                \
        SPLIT2(hw[4], lw[4], pa[2].x, pa[2].y);                                \
        SPLIT2(hw[5], lw[5], pa[2].z, pa[2].w);                                \
        SPLIT2(hw[6], lw[6], pa[3].x, pa[3].y);                                \
        SPLIT2(hw[7], lw[7], pa[3].z, pa[3].w);                                \
        *(uint4*)(a_st + boff)      = make_uint4(hw[0],hw[1],hw[2],hw[3]);     \
        *(uint4*)(a_st + boff + 16) = make_uint4(hw[4],hw[5],hw[6],hw[7]);     \
        *(uint4*)(a_st + boff + A_ARR)      = make_uint4(lw[0],lw[1],lw[2],lw[3]); \
        *(uint4*)(a_st + boff + A_ARR + 16) = make_uint4(lw[4],lw[5],lw[6],lw[7]); \
        SPLIT2(hw[0], lw[0], pb[0].x, pb[0].y);                                \
        SPLIT2(hw[1], lw[1], pb[0].z, pb[0].w);                                \
        SPLIT2(hw[2], lw[2], pb[1].x, pb[1].y);                                \
        SPLIT2(hw[3], lw[3], pb[1].z, pb[1].w);                                \
        SPLIT2(hw[4], lw[4], pb[2].x, pb[2].y);                                \
        SPLIT2(hw[5], lw[5], pb[2].z, pb[2].w);                                \
        SPLIT2(hw[6], lw[6], pb[3].x, pb[3].y);                                \
        SPLIT2(hw[7], lw[7], pb[3].z, pb[3].w);                                \
        *(uint4*)(b_st + boff)      = make_uint4(hw[0],hw[1],hw[2],hw[3]);     \
        *(uint4*)(b_st + boff + 16) = make_uint4(hw[4],hw[5],hw[6],hw[7]);     \
        *(uint4*)(b_st + boff + B_ARR)      = make_uint4(lw[0],lw[1],lw[2],lw[3]); \
        *(uint4*)(b_st + boff + B_ARR + 16) = make_uint4(lw[4],lw[5],lw[6],lw[7]); \
        __syncthreads();                                                       \
        if (c + 1 < (NCH)) {                                                   \
            const float* asrc = aptr + (c + 1) * KC + akh;                     \
            const float* bsrc = bsrc0 + (size_t)(c + 1) * KC * (LDB);          \
            _Pragma("unroll")                                                  \
            for (int m = 0; m < 4; m++) {                                      \
                pa[m] = *(const float4*)(asrc + m * 4);                        \
                pb[m] = *(const float4*)(bsrc + m * 4);                        \
            }                                                                  \
        }                                                                      \
        _Pragma("unroll")                                                      \
        for (int slab = 0; slab < 2; slab++) {                                 \
            uint32_t ah[2][4], al[2][4];                                       \
            _Pragma("unroll")                                                  \
            for (int i = 0; i < 2; i++) {                                      \
                uint32_t aa = a_lm + boff + (uint32_t)(i * 1280 + slab * 32);  \
                LDMX4(ah[i][0], ah[i][1], ah[i][2], ah[i][3], aa);             \
                LDMX4(al[i][0], al[i][1], al[i][2], al[i][3], aa + A_ARR);     \
            }                                                                  \
            _Pragma("unroll")                                                  \
            for (int jp = 0; jp < 4; jp++) {                                   \
                uint32_t bh[4], bl[4];                                         \
                uint32_t ba = b_lm + boff + (uint32_t)(slab * 4352 + jp * 32); \
                LDMX4T(bh[0], bh[1], bh[2], bh[3], ba);                        \
                LDMX4T(bl[0], bl[1], bl[2], bl[3], ba + B_ARR);                \
                _Pragma("unroll")                                              \
                for (int i = 0; i < 2; i++) {                                  \
                    mma_bf16(acc[i][2*jp],     ah[i], bh);                     \
                    mma_bf16(acc[i][2*jp],     al[i], bh);                     \
                    mma_bf16(acc[i][2*jp],     ah[i], bl);                     \
                    mma_bf16(acc[i][2*jp + 1], ah[i], bh + 2);                 \
                    mma_bf16(acc[i][2*jp + 1], al[i], bh + 2);                 \
                    mma_bf16(acc[i][2*jp + 1], ah[i], bl + 2);                 \
                }                                                              \
            }                                                                  \
        }                                                                      \
    }

// ---------------------------------------------------------------------------
// 3) grouped GEMM1: h = silu(gather(x) @ W1 + b1). grid (IDIM/128=32, 144)
// ---------------------------------------------------------------------------
__global__ void __launch_bounds__(256)
gemm1_k(const float* __restrict__ x,  const float* __restrict__ ew1,
        const float* __restrict__ eb1, const float* __restrict__ sw1,
        const float* __restrict__ sb1) {
    extern __shared__ char smem[];
    const int t = blockIdx.y, n0 = blockIdx.x * 128, tid = threadIdx.x;
    int* s_tok = (int*)(smem + OFF_TOK);

    const float* W; const float* bias;
    if (t < 128) {
        int e = t >> 4;
        int cnt = g_cnt[e];
        int lr0 = (t & 15) * 128;
        if (lr0 >= cnt) return;
        W = ew1 + (size_t)e * CDIM * IDIM;
        bias = eb1 + (size_t)e * IDIM;
        if (tid < 128) {
            int lr = lr0 + tid;
            s_tok[tid] = (lr < cnt) ? g_ptok[e * SEG + lr] : 0;
        }
    } else {
        W = sw1; bias = sb1;
        if (tid < 128) s_tok[tid] = (t - 128) * 128 + tid;
    }
    __syncthreads();

    uint32_t smem_base = smem_u32(smem);
    const float* aptr = x + (size_t)s_tok[tid >> 1] * CDIM;

    GEMM_MAINLOOP(IDIM, CDIM / KC)

#pragma unroll
    for (int i = 0; i < 2; i++)
#pragma unroll
        for (int j = 0; j < 8; j++) {
            const int row0 = t * 128 + wm * 32 + i * 16 + g;
            const int col = n0 + wn * 64 + j * 8 + 2 * tt;
            float b0 = bias[col], b1 = bias[col + 1];
            float v0 = acc[i][j][0] + b0, v1 = acc[i][j][1] + b1;
            float v2 = acc[i][j][2] + b0, v3 = acc[i][j][3] + b1;
            float2 lo, hi;
            lo.x = v0 / (1.0f + __expf(-v0)); lo.y = v1 / (1.0f + __expf(-v1));
            hi.x = v2 / (1.0f + __expf(-v2)); hi.y = v3 / (1.0f + __expf(-v3));
            *(float2*)(g_h + (size_t)row0 * IDIM + col) = lo;
            *(float2*)(g_h + (size_t)(row0 + 8) * IDIM + col) = hi;
        }
}

// ---------------------------------------------------------------------------
// 4) grouped GEMM2: eo = h @ W2 + b2. grid (CDIM/128=8, 144). K=4096
// ---------------------------------------------------------------------------
__global__ void __launch_bounds__(256)
gemm2_k(const float* __restrict__ ew2, const float* __restrict__ eb2,
        const float* __restrict__ sw2, const float* __restrict__ sb2) {
    extern __shared__ char smem[];
    const int t = blockIdx.y, n0 = blockIdx.x * 128, tid = threadIdx.x;

    const float* W; const float* bias;
    if (t < 128) {
        int e = t >> 4;
        if ((t & 15) * 128 >= g_cnt[e]) return;
        W = ew2 + (size_t)e * IDIM * CDIM;
        bias = eb2 + (size_t)e * CDIM;
    } else {
        W = sw2; bias = sb2;
    }
    __syncthreads();

    uint32_t smem_base = smem_u32(smem);
    const float* aptr = g_h + (size_t)(t * 128 + (tid >> 1)) * IDIM;

    GEMM_MAINLOOP(CDIM, IDIM / KC)

#pragma unroll
    for (int i = 0; i < 2; i++)
#pragma unroll
        for (int j = 0; j < 8; j++) {
            const int row0 = t * 128 + wm * 32 + i * 16 + g;
            const int col = n0 + wn * 64 + j * 8 + 2 * tt;
            float b0 = bias[col], b1 = bias[col + 1];
            float2 lo, hi;
            lo.x = acc[i][j][0] + b0; lo.y = acc[i][j][1] + b1;
            hi.x = acc[i][j][2] + b0; hi.y = acc[i][j][3] + b1;
            *(float2*)(g_eo + (size_t)row0 * CDIM + col) = lo;
            *(float2*)(g_eo + (size_t)(row0 + 8) * CDIM + col) = hi;
        }
}

// ---------------------------------------------------------------------------
// 5) combine: out[n] = eo[shared_n] + w0*eo[pos0] + w1*eo[pos1]
// ---------------------------------------------------------------------------
__global__ void combine_kernel(float* __restrict__ out) {
    int gid = blockIdx.x * 256 + threadIdx.x;
    int n = gid >> 8, c4 = gid & 255;
    const float4* eo = (const float4*)g_eo;
    float4 o = eo[(size_t)(R_EXP + n) * (CDIM / 4) + c4];
    int   p0 = g_tpos[n * 2],     p1 = g_tpos[n * 2 + 1];
    float w0 = g_tw[n * 2],       w1 = g_tw[n * 2 + 1];
    float4 a = eo[(size_t)p0 * (CDIM / 4) + c4];
    float4 b = eo[(size_t)p1 * (CDIM / 4) + c4];
    o.x += w0 * a.x + w1 * b.x;
    o.y += w0 * a.y + w1 * b.y;
    o.z += w0 * a.z + w1 * b.z;
    o.w += w0 * a.w + w1 * b.w;
    ((float4*)out)[gid] = o;
}

// ---------------------------------------------------------------------------
extern "C" void kernel_launch(void* const* d_in, const int* in_sizes, int n_in,
                              void* d_out, int out_size) {
    const float* x   = (const float*)d_in[0];
    const float* rw1 = (const float*)d_in[1];
    const float* rb1 = (const float*)d_in[2];
    const float* rw2 = (const float*)d_in[3];
    const float* rb2 = (const float*)d_in[4];
    const float* ew1 = (const float*)d_in[5];
    const float* eb1 = (const float*)d_in[6];
    const float* ew2 = (const float*)d_in[7];
    const float* eb2 = (const float*)d_in[8];
    const float* sw1 = (const float*)d_in[9];
    const float* sb1 = (const float*)d_in[10];
    const float* sw2 = (const float*)d_in[11];
    const float* sb2 = (const float*)d_in[12];
    float* out = (float*)d_out;

    static bool attr_done = false;
    if (!attr_done) {
        cudaFuncSetAttribute(gemm1_k, cudaFuncAttributeMaxDynamicSharedMemorySize, SMEM_TOTAL);
        cudaFuncSetAttribute(gemm2_k, cudaFuncAttributeMaxDynamicSharedMemorySize, SMEM_TOTAL);
        attr_done = true;
    }

    init_kernel<<<1, 32>>>();
    router_gemm<<<dim3(2, 16), 256>>>(x, rw1, rb1);
    route_kernel<<<8, 256>>>(rw2, rb2);
    gemm1_k<<<dim3(IDIM / 128, MT_TOT), 256, SMEM_TOTAL>>>(x, ew1, eb1, sw1, sb1);
    gemm2_k<<<dim3(CDIM / 128, MT_TOT), 256, SMEM_TOTAL>>>(ew2, eb2, sw2, sb2);
    combine_kernel<<<N_TOK * CDIM / 4 / 256, 256>>>(out);
}

// round 12
// speedup vs baseline: 1.1853x; 1.1000x over previous
#include <cuda_runtime.h>
#include <math.h>
#include <stdint.h>

// Problem dims
#define N_TOK 2048
#define CDIM  1024
#define RH    256
#define NE    8
#define IDIM  4096
#define SEG   2048
#define R_EXP (NE*SEG)          // 16384
#define R_TOT (R_EXP + N_TOK)   // 18432
#define MT_TOT (R_TOT/128)      // 144 row tiles
#define KC 32                   // K chunk
#define RKS 8                   // router K-split

// SMEM layout (bytes). Per buffer: A_hi[128][40]bf16, A_lo, B_hi[32][136]bf16, B_lo
#define OFF_TOK  64
#define OFF_AHI  1024
#define A_ARR    10240                  // 128*80
#define OFF_ALO  (OFF_AHI + A_ARR)      // 11264
#define OFF_BHI  (OFF_ALO + A_ARR)      // 21504
#define B_ARR    8704                   // 32*272
#define OFF_BLO  (OFF_BHI + B_ARR)      // 30208
#define SBUF     (2*A_ARR + 2*B_ARR)    // 37888 (one buffer)
#define SMEM_TOTAL (1024 + 2*SBUF)      // 76800

// Scratch
__device__ float g_y1p[(size_t)RKS * N_TOK * RH]; // router split-K partials
__device__ float g_y1[N_TOK * RH];                // router hidden (relu'd)
__device__ float g_h [(size_t)R_TOT * IDIM];      // silu(x@W1+b1)
__device__ float g_eo[(size_t)R_TOT * CDIM];      // h@W2+b2 per row
__device__ int   g_cnt[NE];
__device__ int   g_ptok[R_EXP];
__device__ int   g_tpos[N_TOK * 2];
__device__ float g_tw  [N_TOK * 2];

// ---------------------------------------------------------------------------
// helpers (all legal on base sm_103 target)
// ---------------------------------------------------------------------------
__device__ __forceinline__ void mma_bf16(float* d, const uint32_t* a, const uint32_t* b) {
    asm volatile(
        "mma.sync.aligned.m16n8k16.row.col.f32.bf16.bf16.f32 "
        "{%0,%1,%2,%3},{%4,%5,%6,%7},{%8,%9},{%0,%1,%2,%3};\n"
        : "+f"(d[0]), "+f"(d[1]), "+f"(d[2]), "+f"(d[3])
        : "r"(a[0]), "r"(a[1]), "r"(a[2]), "r"(a[3]), "r"(b[0]), "r"(b[1]));
}
#define LDMX4(r0,r1,r2,r3,addr) \
    asm volatile("ldmatrix.sync.aligned.m8n8.x4.shared.b16 {%0,%1,%2,%3}, [%4];" \
        : "=r"(r0),"=r"(r1),"=r"(r2),"=r"(r3) : "r"(addr))
#define LDMX4T(r0,r1,r2,r3,addr) \
    asm volatile("ldmatrix.sync.aligned.m8n8.x4.trans.shared.b16 {%0,%1,%2,%3}, [%4];" \
        : "=r"(r0),"=r"(r1),"=r"(r2),"=r"(r3) : "r"(addr))

// Split (v0, v1) fp32 pair into packed bf16x2 hi word + bf16x2 lo-residual word.
#define SPLIT2(hw, lw, v0, v1) do { \
    asm("cvt.rn.bf16x2.f32 %0, %1, %2;" : "=r"(hw) : "f"(v1), "f"(v0)); \
    float _h0 = __uint_as_float((hw) << 16); \
    float _h1 = __uint_as_float((hw) & 0xffff0000u); \
    float _r0 = (v0) - _h0, _r1 = (v1) - _h1; \
    asm("cvt.rn.bf16x2.f32 %0, %1, %2;" : "=r"(lw) : "f"(_r1), "f"(_r0)); \
} while (0)

__device__ __forceinline__ uint32_t smem_u32(const void* p) {
    uint32_t a;
    asm("{ .reg .u64 t; cvta.to.shared.u64 t, %1; cvt.u32.u64 %0, t; }"
        : "=r"(a) : "l"(p));
    return a;
}

// ---------------------------------------------------------------------------
// 0) init counters
// ---------------------------------------------------------------------------
__global__ void init_kernel() {
    if (threadIdx.x < NE) g_cnt[threadIdx.x] = 0;
}

// ---------------------------------------------------------------------------
// 1) router GEMM split-K=8 (deterministic partials): y1p[s] = x[:,ks] @ rw1[ks,:]
//    grid (2, 16, 8) = 256 CTAs
// ---------------------------------------------------------------------------
__global__ void __launch_bounds__(256, 2)
router_gemm(const float* __restrict__ x, const float* __restrict__ rw1) {
    __shared__ float As[8][128];
    __shared__ float Bs[8][128];
    const int tid = threadIdx.x;
    const int m0 = blockIdx.y * 128;
    const int n0 = blockIdx.x * 128;
    const int ks = blockIdx.z * (CDIM / RKS);

    const int ar = tid >> 1, kh = (tid & 1) * 4;
    const int kb = tid >> 5, bn = (tid & 31) * 4;
    const float* arow = x + (size_t)(m0 + ar) * CDIM + ks;
    const float* bptr = rw1 + (size_t)(ks + kb) * RH + n0 + bn;
    const int tm = (tid >> 4) * 8, tn = (tid & 15) * 8;

    float acc[8][8];
#pragma unroll
    for (int i = 0; i < 8; i++)
#pragma unroll
        for (int j = 0; j < 8; j++) acc[i][j] = 0.0f;

    for (int k0 = 0; k0 < CDIM / RKS; k0 += 8) {
        float4 av = *(const float4*)(arow + k0 + kh);
        As[kh + 0][ar] = av.x; As[kh + 1][ar] = av.y;
        As[kh + 2][ar] = av.z; As[kh + 3][ar] = av.w;
        *(float4*)&Bs[kb][bn] = *(const float4*)(bptr + (size_t)k0 * RH);
        __syncthreads();
#pragma unroll
        for (int kk = 0; kk < 8; kk++) {
            float a[8], b[8];
#pragma unroll
            for (int i = 0; i < 8; i++) a[i] = As[kk][tm + i];
#pragma unroll
            for (int j = 0; j < 8; j++) b[j] = Bs[kk][tn + j];
#pragma unroll
            for (int i = 0; i < 8; i++)
#pragma unroll
                for (int j = 0; j < 8; j++) acc[i][j] += a[i] * b[j];
        }
        __syncthreads();
    }
#pragma unroll
    for (int i = 0; i < 8; i++) {
        float* dst = g_y1p + ((size_t)blockIdx.z * N_TOK + m0 + tm + i) * RH + n0 + tn;
#pragma unroll
        for (int j = 0; j < 8; j++) dst[j] = acc[i][j];
    }
}

// ---------------------------------------------------------------------------
// 1b) sum partials + rb1 + relu -> g_y1. grid 512 x 256, float4 per thread.
// ---------------------------------------------------------------------------
__global__ void sum_relu_kernel(const float* __restrict__ rb1) {
    int i4 = blockIdx.x * 256 + threadIdx.x;          // < N_TOK*RH/4 = 131072
    const float4* p = (const float4*)g_y1p;
    float4 a = p[i4];
#pragma unroll
    for (int s = 1; s < RKS; s++) {
        float4 v = p[(size_t)s * (N_TOK * RH / 4) + i4];
        a.x += v.x; a.y += v.y; a.z += v.z; a.w += v.w;
    }
    float4 b = ((const float4*)rb1)[i4 & (RH / 4 - 1)];
    a.x = fmaxf(a.x + b.x, 0.0f);
    a.y = fmaxf(a.y + b.y, 0.0f);
    a.z = fmaxf(a.z + b.z, 0.0f);
    a.w = fmaxf(a.w + b.w, 0.0f);
    ((float4*)g_y1)[i4] = a;
}

// ---------------------------------------------------------------------------
// 2) routing (R6-validated): logits -> softmax -> top2 -> scatter + positions
// ---------------------------------------------------------------------------
__global__ void route_kernel(const float* __restrict__ rw2,
                             const float* __restrict__ rb2) {
    __shared__ float s_w[RH * NE];
    __shared__ float s_b[NE];
    const int tid = threadIdx.x;
    for (int i = tid; i < RH * NE; i += 256) s_w[i] = rw2[i];
    if (tid < NE) s_b[tid] = rb2[tid];
    __syncthreads();

    const int n = blockIdx.x * 256 + tid;
    const float* y = g_y1 + (size_t)n * RH;

    float acc[NE];
#pragma unroll
    for (int e = 0; e < NE; e++) acc[e] = s_b[e];
    for (int c = 0; c < RH; c++) {
        float v = y[c];
#pragma unroll
        for (int e = 0; e < NE; e++) acc[e] += v * s_w[c * NE + e];
    }

    float m = acc[0];
#pragma unroll
    for (int e = 1; e < NE; e++) m = fmaxf(m, acc[e]);
    float s = 0.0f, g[NE];
#pragma unroll
    for (int e = 0; e < NE; e++) { g[e] = expf(acc[e] - m); s += g[e]; }
    float inv = 1.0f / s;
#pragma unroll
    for (int e = 0; e < NE; e++) g[e] *= inv;

    int i1 = 0; float g1 = g[0];
#pragma unroll
    for (int e = 1; e < NE; e++) if (g[e] > g1) { g1 = g[e]; i1 = e; }
    int i2 = -1; float g2 = -1.0f;
#pragma unroll
    for (int e = 0; e < NE; e++)
        if (e != i1 && g[e] > g2) { g2 = g[e]; i2 = e; }

    float t  = expf((g2 - g1) * 0.5f);
    float d  = 1.0f / (1.0f + t);
    float w1 = d, w2 = t * d;

    int p1 = atomicAdd(&g_cnt[i1], 1);
    g_ptok[i1 * SEG + p1] = n;
    g_tpos[n * 2] = i1 * SEG + p1; g_tw[n * 2] = w1;
    int p2 = atomicAdd(&g_cnt[i2], 1);
    g_ptok[i2 * SEG + p2] = n;
    g_tpos[n * 2 + 1] = i2 * SEG + p2; g_tw[n * 2 + 1] = w2;
}

// ---------------------------------------------------------------------------
// bf16x3 HMMA mainloop (R11-validated, verbatim).
// ---------------------------------------------------------------------------
#define GEMM_MAINLOOP(LDB, NCH)                                                \
    const int wid = tid >> 5, lane = tid & 31;                                 \
    const int wm = wid & 3, wn = wid >> 2;                                     \
    const int g = lane >> 2, tt = lane & 3;                                    \
    const int akh = (tid & 1) * 16;                                            \
    const int bkr = tid >> 3, bng = (tid & 7) * 16;                            \
    char* a_st = smem + OFF_AHI + (tid >> 1) * 80 + akh * 2;                   \
    char* b_st = smem + OFF_BHI + bkr * 272 + bng * 2;                         \
    const float* bsrc0 = W + (size_t)bkr * (LDB) + n0 + bng;                   \
    const uint32_t a_lm = smem_base + OFF_AHI +                                \
        (uint32_t)((wm * 32 + (lane & 15)) * 80 + (lane >> 4) * 16);           \
    const uint32_t b_lm = smem_base + OFF_BHI +                                \
        (uint32_t)(((lane & 7) + ((lane >> 3) & 1) * 8) * 272                  \
                   + (lane >> 4) * 16 + wn * 128);                             \
    float acc[2][8][4];                                                        \
    _Pragma("unroll")                                                          \
    for (int i = 0; i < 2; i++)                                                \
        _Pragma("unroll")                                                      \
        for (int j = 0; j < 8; j++)                                            \
            _Pragma("unroll")                                                  \
            for (int q = 0; q < 4; q++) acc[i][j][q] = 0.0f;                   \
    float4 pa[4], pb[4];                                                       \
    _Pragma("unroll")                                                          \
    for (int m = 0; m < 4; m++) {                                              \
        pa[m] = *(const float4*)(aptr + akh + m * 4);                          \
        pb[m] = *(const float4*)(bsrc0 + m * 4);                               \
    }                                                                          \
    for (int c = 0; c < (NCH); c++) {                                          \
        const uint32_t boff = (uint32_t)(c & 1) * SBUF;                        \
        uint32_t hw[8], lw[8];                                                 \
        SPLIT2(hw[0], lw[0], pa[0].x, pa[0].y);                                \
        SPLIT2(hw[1], lw[1], pa[0].z, pa[0].w);                                \
        SPLIT2(hw[2], lw[2], pa[1].x, pa[1].y);                                \
        SPLIT2(hw[3], lw[3], pa[1].z, pa[1].w);                                \
        SPLIT2(hw[4], lw[4], pa[2].x, pa[2].y);                                \
        SPLIT2(hw[5], lw[5], pa[2].z, pa[2].w);                                \
        SPLIT2(hw[6], lw[6], pa[3].x, pa[3].y);                                \
        SPLIT2(hw[7], lw[7], pa[3].z, pa[3].w);                                \
        *(uint4*)(a_st + boff)      = make_uint4(hw[0],hw[1],hw[2],hw[3]);     \
        *(uint4*)(a_st + boff + 16) = make_uint4(hw[4],hw[5],hw[6],hw[7]);     \
        *(uint4*)(a_st + boff + A_ARR)      = make_uint4(lw[0],lw[1],lw[2],lw[3]); \
        *(uint4*)(a_st + boff + A_ARR + 16) = make_uint4(lw[4],lw[5],lw[6],lw[7]); \
        SPLIT2(hw[0], lw[0], pb[0].x, pb[0].y);                                \
        SPLIT2(hw[1], lw[1], pb[0].z, pb[0].w);                                \
        SPLIT2(hw[2], lw[2], pb[1].x, pb[1].y);                                \
        SPLIT2(hw[3], lw[3], pb[1].z, pb[1].w);                                \
        SPLIT2(hw[4], lw[4], pb[2].x, pb[2].y);                                \
        SPLIT2(hw[5], lw[5], pb[2].z, pb[2].w);                                \
        SPLIT2(hw[6], lw[6], pb[3].x, pb[3].y);                                \
        SPLIT2(hw[7], lw[7], pb[3].z, pb[3].w);                                \
        *(uint4*)(b_st + boff)      = make_uint4(hw[0],hw[1],hw[2],hw[3]);     \
        *(uint4*)(b_st + boff + 16) = make_uint4(hw[4],hw[5],hw[6],hw[7]);     \
        *(uint4*)(b_st + boff + B_ARR)      = make_uint4(lw[0],lw[1],lw[2],lw[3]); \
        *(uint4*)(b_st + boff + B_ARR + 16) = make_uint4(lw[4],lw[5],lw[6],lw[7]); \
        __syncthreads();                                                       \
        if (c + 1 < (NCH)) {                                                   \
            const float* asrc = aptr + (c + 1) * KC + akh;                     \
            const float* bsrc = bsrc0 + (size_t)(c + 1) * KC * (LDB);          \
            _Pragma("unroll")                                                  \
            for (int m = 0; m < 4; m++) {                                      \
                pa[m] = *(const float4*)(asrc + m * 4);                        \
                pb[m] = *(const float4*)(bsrc + m * 4);                        \
            }                                                                  \
        }                                                                      \
        _Pragma("unroll")                                                      \
        for (int slab = 0; slab < 2; slab++) {                                 \
            uint32_t ah[2][4], al[2][4];                                       \
            _Pragma("unroll")                                                  \
            for (int i = 0; i < 2; i++) {                                      \
                uint32_t aa = a_lm + boff + (uint32_t)(i * 1280 + slab * 32);  \
                LDMX4(ah[i][0], ah[i][1], ah[i][2], ah[i][3], aa);             \
                LDMX4(al[i][0], al[i][1], al[i][2], al[i][3], aa + A_ARR);     \
            }                                                                  \
            _Pragma("unroll")                                                  \
            for (int jp = 0; jp < 4; jp++) {                                   \
                uint32_t bh[4], bl[4];                                         \
                uint32_t ba = b_lm + boff + (uint32_t)(slab * 4352 + jp * 32); \
                LDMX4T(bh[0], bh[1], bh[2], bh[3], ba);                        \
                LDMX4T(bl[0], bl[1], bl[2], bl[3], ba + B_ARR);                \
                _Pragma("unroll")                                              \
                for (int i = 0; i < 2; i++) {                                  \
                    mma_bf16(acc[i][2*jp],     ah[i], bh);                     \
                    mma_bf16(acc[i][2*jp],     al[i], bh);                     \
                    mma_bf16(acc[i][2*jp],     ah[i], bl);                     \
                    mma_bf16(acc[i][2*jp + 1], ah[i], bh + 2);                 \
                    mma_bf16(acc[i][2*jp + 1], al[i], bh + 2);                 \
                    mma_bf16(acc[i][2*jp + 1], ah[i], bl + 2);                 \
                }                                                              \
            }                                                                  \
        }                                                                      \
    }

// ---------------------------------------------------------------------------
// 3) grouped GEMM1: h = silu(gather(x) @ W1 + b1). grid (IDIM/128=32, 144)
// ---------------------------------------------------------------------------
__global__ void __launch_bounds__(256)
gemm1_k(const float* __restrict__ x,  const float* __restrict__ ew1,
        const float* __restrict__ eb1, const float* __restrict__ sw1,
        const float* __restrict__ sb1) {
    extern __shared__ char smem[];
    const int t = blockIdx.y, n0 = blockIdx.x * 128, tid = threadIdx.x;
    int* s_tok = (int*)(smem + OFF_TOK);

    const float* W; const float* bias;
    if (t < 128) {
        int e = t >> 4;
        int cnt = g_cnt[e];
        int lr0 = (t & 15) * 128;
        if (lr0 >= cnt) return;
        W = ew1 + (size_t)e * CDIM * IDIM;
        bias = eb1 + (size_t)e * IDIM;
        if (tid < 128) {
            int lr = lr0 + tid;
            s_tok[tid] = (lr < cnt) ? g_ptok[e * SEG + lr] : 0;
        }
    } else {
        W = sw1; bias = sb1;
        if (tid < 128) s_tok[tid] = (t - 128) * 128 + tid;
    }
    __syncthreads();

    uint32_t smem_base = smem_u32(smem);
    const float* aptr = x + (size_t)s_tok[tid >> 1] * CDIM;

    GEMM_MAINLOOP(IDIM, CDIM / KC)

#pragma unroll
    for (int i = 0; i < 2; i++)
#pragma unroll
        for (int j = 0; j < 8; j++) {
            const int row0 = t * 128 + wm * 32 + i * 16 + g;
            const int col = n0 + wn * 64 + j * 8 + 2 * tt;
            float b0 = bias[col], b1 = bias[col + 1];
            float v0 = acc[i][j][0] + b0, v1 = acc[i][j][1] + b1;
            float v2 = acc[i][j][2] + b0, v3 = acc[i][j][3] + b1;
            float2 lo, hi;
            lo.x = v0 / (1.0f + __expf(-v0)); lo.y = v1 / (1.0f + __expf(-v1));
            hi.x = v2 / (1.0f + __expf(-v2)); hi.y = v3 / (1.0f + __expf(-v3));
            *(float2*)(g_h + (size_t)row0 * IDIM + col) = lo;
            *(float2*)(g_h + (size_t)(row0 + 8) * IDIM + col) = hi;
        }
}

// ---------------------------------------------------------------------------
// 4) grouped GEMM2: eo = h @ W2 + b2. grid (CDIM/128=8, 144). K=4096
// ---------------------------------------------------------------------------
__global__ void __launch_bounds__(256)
gemm2_k(const float* __restrict__ ew2, const float* __restrict__ eb2,
        const float* __restrict__ sw2, const float* __restrict__ sb2) {
    extern __shared__ char smem[];
    const int t = blockIdx.y, n0 = blockIdx.x * 128, tid = threadIdx.x;

    const float* W; const float* bias;
    if (t < 128) {
        int e = t >> 4;
        if ((t & 15) * 128 >= g_cnt[e]) return;
        W = ew2 + (size_t)e * IDIM * CDIM;
        bias = eb2 + (size_t)e * CDIM;
    } else {
        W = sw2; bias = sb2;
    }
    __syncthreads();

    uint32_t smem_base = smem_u32(smem);
    const float* aptr = g_h + (size_t)(t * 128 + (tid >> 1)) * IDIM;

    GEMM_MAINLOOP(CDIM, IDIM / KC)

#pragma unroll
    for (int i = 0; i < 2; i++)
#pragma unroll
        for (int j = 0; j < 8; j++) {
            const int row0 = t * 128 + wm * 32 + i * 16 + g;
            const int col = n0 + wn * 64 + j * 8 + 2 * tt;
            float b0 = bias[col], b1 = bias[col + 1];
            float2 lo, hi;
            lo.x = acc[i][j][0] + b0; lo.y = acc[i][j][1] + b1;
            hi.x = acc[i][j][2] + b0; hi.y = acc[i][j][3] + b1;
            *(float2*)(g_eo + (size_t)row0 * CDIM + col) = lo;
            *(float2*)(g_eo + (size_t)(row0 + 8) * CDIM + col) = hi;
        }
}

// ---------------------------------------------------------------------------
// 5) combine: out[n] = eo[shared_n] + w0*eo[pos0] + w1*eo[pos1]
// ---------------------------------------------------------------------------
__global__ void combine_kernel(float* __restrict__ out) {
    int gid = blockIdx.x * 256 + threadIdx.x;
    int n = gid >> 8, c4 = gid & 255;
    const float4* eo = (const float4*)g_eo;
    float4 o = eo[(size_t)(R_EXP + n) * (CDIM / 4) + c4];
    int   p0 = g_tpos[n * 2],     p1 = g_tpos[n * 2 + 1];
    float w0 = g_tw[n * 2],       w1 = g_tw[n * 2 + 1];
    float4 a = eo[(size_t)p0 * (CDIM / 4) + c4];
    float4 b = eo[(size_t)p1 * (CDIM / 4) + c4];
    o.x += w0 * a.x + w1 * b.x;
    o.y += w0 * a.y + w1 * b.y;
    o.z += w0 * a.z + w1 * b.z;
    o.w += w0 * a.w + w1 * b.w;
    ((float4*)out)[gid] = o;
}

// ---------------------------------------------------------------------------
extern "C" void kernel_launch(void* const* d_in, const int* in_sizes, int n_in,
                              void* d_out, int out_size) {
    const float* x   = (const float*)d_in[0];
    const float* rw1 = (const float*)d_in[1];
    const float* rb1 = (const float*)d_in[2];
    const float* rw2 = (const float*)d_in[3];
    const float* rb2 = (const float*)d_in[4];
    const float* ew1 = (const float*)d_in[5];
    const float* eb1 = (const float*)d_in[6];
    const float* ew2 = (const float*)d_in[7];
    const float* eb2 = (const float*)d_in[8];
    const float* sw1 = (const float*)d_in[9];
    const float* sb1 = (const float*)d_in[10];
    const float* sw2 = (const float*)d_in[11];
    const float* sb2 = (const float*)d_in[12];
    float* out = (float*)d_out;

    static bool attr_done = false;
    if (!attr_done) {
        cudaFuncSetAttribute(gemm1_k, cudaFuncAttributeMaxDynamicSharedMemorySize, SMEM_TOTAL);
        cudaFuncSetAttribute(gemm2_k, cudaFuncAttributeMaxDynamicSharedMemorySize, SMEM_TOTAL);
        attr_done = true;
    }

    init_kernel<<<1, 32>>>();
    router_gemm<<<dim3(2, 16, RKS), 256>>>(x, rw1);
    sum_relu_kernel<<<N_TOK * RH / 4 / 256, 256>>>(rb1);
    route_kernel<<<8, 256>>>(rw2, rb2);
    gemm1_k<<<dim3(IDIM / 128, MT_TOT), 256, SMEM_TOTAL>>>(x, ew1, eb1, sw1, sb1);
    gemm2_k<<<dim3(CDIM / 128, MT_TOT), 256, SMEM_TOTAL>>>(ew2, eb2, sw2, sb2);
    combine_kernel<<<N_TOK * CDIM / 4 / 256, 256>>>(out);
}

// round 13
// speedup vs baseline: 1.2239x; 1.0326x over previous
#include <cuda_runtime.h>
#include <math.h>
#include <stdint.h>

// Problem dims
#define N_TOK 2048
#define CDIM  1024
#define RH    256
#define NE    8
#define IDIM  4096
#define SEG   2048
#define R_EXP (NE*SEG)          // 16384
#define R_TOT (R_EXP + N_TOK)   // 18432
#define MT_TOT (R_TOT/128)      // 144 row tiles
#define KC 32                   // K chunk
#define RKS 8                   // router K-split

// SMEM layout (bytes). Per buffer: A_hi[128][40]bf16, A_lo, B_hi[32][136]bf16, B_lo
#define OFF_TOK  64
#define OFF_AHI  1024
#define A_ARR    10240                  // 128*80
#define OFF_ALO  (OFF_AHI + A_ARR)      // 11264
#define OFF_BHI  (OFF_ALO + A_ARR)      // 21504
#define B_ARR    8704                   // 32*272
#define OFF_BLO  (OFF_BHI + B_ARR)      // 30208
#define SBUF     (2*A_ARR + 2*B_ARR)    // 37888 (one buffer)
#define SMEM_TOTAL (1024 + 2*SBUF)      // 76800

// Scratch
__device__ float g_y1p[(size_t)RKS * N_TOK * RH]; // router split-K partials
__device__ float g_y1[N_TOK * RH];                // router hidden (relu'd)
__device__ float g_h [(size_t)R_TOT * IDIM];      // silu(x@W1+b1)
__device__ float g_eo[(size_t)R_TOT * CDIM];      // h@W2+b2 per row
__device__ int   g_cnt[NE];
__device__ int   g_ptok[R_EXP];
__device__ int   g_tpos[N_TOK * 2];
__device__ float g_tw  [N_TOK * 2];

// ---------------------------------------------------------------------------
// helpers (all legal on base sm_103 target)
// ---------------------------------------------------------------------------
__device__ __forceinline__ void mma_bf16(float* d, const uint32_t* a, const uint32_t* b) {
    asm volatile(
        "mma.sync.aligned.m16n8k16.row.col.f32.bf16.bf16.f32 "
        "{%0,%1,%2,%3},{%4,%5,%6,%7},{%8,%9},{%0,%1,%2,%3};\n"
        : "+f"(d[0]), "+f"(d[1]), "+f"(d[2]), "+f"(d[3])
        : "r"(a[0]), "r"(a[1]), "r"(a[2]), "r"(a[3]), "r"(b[0]), "r"(b[1]));
}
#define LDMX4(r0,r1,r2,r3,addr) \
    asm volatile("ldmatrix.sync.aligned.m8n8.x4.shared.b16 {%0,%1,%2,%3}, [%4];" \
        : "=r"(r0),"=r"(r1),"=r"(r2),"=r"(r3) : "r"(addr))
#define LDMX4T(r0,r1,r2,r3,addr) \
    asm volatile("ldmatrix.sync.aligned.m8n8.x4.trans.shared.b16 {%0,%1,%2,%3}, [%4];" \
        : "=r"(r0),"=r"(r1),"=r"(r2),"=r"(r3) : "r"(addr))

// Split (v0, v1) fp32 pair into packed bf16x2 hi word + bf16x2 lo-residual word.
#define SPLIT2(hw, lw, v0, v1) do { \
    asm("cvt.rn.bf16x2.f32 %0, %1, %2;" : "=r"(hw) : "f"(v1), "f"(v0)); \
    float _h0 = __uint_as_float((hw) << 16); \
    float _h1 = __uint_as_float((hw) & 0xffff0000u); \
    float _r0 = (v0) - _h0, _r1 = (v1) - _h1; \
    asm("cvt.rn.bf16x2.f32 %0, %1, %2;" : "=r"(lw) : "f"(_r1), "f"(_r0)); \
} while (0)

__device__ __forceinline__ uint32_t smem_u32(const void* p) {
    uint32_t a;
    asm("{ .reg .u64 t; cvta.to.shared.u64 t, %1; cvt.u32.u64 %0, t; }"
        : "=r"(a) : "l"(p));
    return a;
}

// ---------------------------------------------------------------------------
// 0) init counters
// ---------------------------------------------------------------------------
__global__ void init_kernel() {
    if (threadIdx.x < NE) g_cnt[threadIdx.x] = 0;
}

// ---------------------------------------------------------------------------
// 1) router GEMM split-K=8 (deterministic partials): y1p[s] = x[:,ks] @ rw1[ks,:]
//    grid (2, 16, 8) = 256 CTAs
// ---------------------------------------------------------------------------
__global__ void __launch_bounds__(256, 2)
router_gemm(const float* __restrict__ x, const float* __restrict__ rw1) {
    __shared__ float As[8][128];
    __shared__ float Bs[8][128];
    const int tid = threadIdx.x;
    const int m0 = blockIdx.y * 128;
    const int n0 = blockIdx.x * 128;
    const int ks = blockIdx.z * (CDIM / RKS);

    const int ar = tid >> 1, kh = (tid & 1) * 4;
    const int kb = tid >> 5, bn = (tid & 31) * 4;
    const float* arow = x + (size_t)(m0 + ar) * CDIM + ks;
    const float* bptr = rw1 + (size_t)(ks + kb) * RH + n0 + bn;
    const int tm = (tid >> 4) * 8, tn = (tid & 15) * 8;

    float acc[8][8];
#pragma unroll
    for (int i = 0; i < 8; i++)
#pragma unroll
        for (int j = 0; j < 8; j++) acc[i][j] = 0.0f;

    for (int k0 = 0; k0 < CDIM / RKS; k0 += 8) {
        float4 av = *(const float4*)(arow + k0 + kh);
        As[kh + 0][ar] = av.x; As[kh + 1][ar] = av.y;
        As[kh + 2][ar] = av.z; As[kh + 3][ar] = av.w;
        *(float4*)&Bs[kb][bn] = *(const float4*)(bptr + (size_t)k0 * RH);
        __syncthreads();
#pragma unroll
        for (int kk = 0; kk < 8; kk++) {
            float a[8], b[8];
#pragma unroll
            for (int i = 0; i < 8; i++) a[i] = As[kk][tm + i];
#pragma unroll
            for (int j = 0; j < 8; j++) b[j] = Bs[kk][tn + j];
#pragma unroll
            for (int i = 0; i < 8; i++)
#pragma unroll
                for (int j = 0; j < 8; j++) acc[i][j] += a[i] * b[j];
        }
        __syncthreads();
    }
#pragma unroll
    for (int i = 0; i < 8; i++) {
        float* dst = g_y1p + ((size_t)blockIdx.z * N_TOK + m0 + tm + i) * RH + n0 + tn;
#pragma unroll
        for (int j = 0; j < 8; j++) dst[j] = acc[i][j];
    }
}

// ---------------------------------------------------------------------------
// 1b) sum partials + rb1 + relu -> g_y1. grid 512 x 256, float4 per thread.
// ---------------------------------------------------------------------------
__global__ void sum_relu_kernel(const float* __restrict__ rb1) {
    int i4 = blockIdx.x * 256 + threadIdx.x;          // < N_TOK*RH/4 = 131072
    const float4* p = (const float4*)g_y1p;
    float4 a = p[i4];
#pragma unroll
    for (int s = 1; s < RKS; s++) {
        float4 v = p[(size_t)s * (N_TOK * RH / 4) + i4];
        a.x += v.x; a.y += v.y; a.z += v.z; a.w += v.w;
    }
    float4 b = ((const float4*)rb1)[i4 & (RH / 4 - 1)];
    a.x = fmaxf(a.x + b.x, 0.0f);
    a.y = fmaxf(a.y + b.y, 0.0f);
    a.z = fmaxf(a.z + b.z, 0.0f);
    a.w = fmaxf(a.w + b.w, 0.0f);
    ((float4*)g_y1)[i4] = a;
}

// ---------------------------------------------------------------------------
// 2) routing (warp-per-token): logits -> softmax -> top2 -> scatter
//    grid 256, block 256 (8 warps = 8 tokens per CTA)
// ---------------------------------------------------------------------------
__global__ void route_kernel(const float* __restrict__ rw2,
                             const float* __restrict__ rb2) {
    __shared__ float s_w[RH * NE];
    __shared__ float s_b[NE];
    const int tid = threadIdx.x;
    for (int i = tid; i < RH * NE; i += 256) s_w[i] = rw2[i];
    if (tid < NE) s_b[tid] = rb2[tid];
    __syncthreads();

    const int n = blockIdx.x * 8 + (tid >> 5);
    const int lane = tid & 31;
    const float* y = g_y1 + (size_t)n * RH;

    float acc[NE];
#pragma unroll
    for (int e = 0; e < NE; e++) acc[e] = 0.0f;
#pragma unroll
    for (int cb = 0; cb < RH; cb += 32) {
        float v = y[cb + lane];
        const float* wrow = s_w + (cb + lane) * NE;
#pragma unroll
        for (int e = 0; e < NE; e++) acc[e] += v * wrow[e];
    }
#pragma unroll
    for (int off = 16; off > 0; off >>= 1)
#pragma unroll
        for (int e = 0; e < NE; e++)
            acc[e] += __shfl_down_sync(0xffffffff, acc[e], off);

    if (lane == 0) {
#pragma unroll
        for (int e = 0; e < NE; e++) acc[e] += s_b[e];
        float m = acc[0];
#pragma unroll
        for (int e = 1; e < NE; e++) m = fmaxf(m, acc[e]);
        float s = 0.0f, g[NE];
#pragma unroll
        for (int e = 0; e < NE; e++) { g[e] = expf(acc[e] - m); s += g[e]; }
        float inv = 1.0f / s;
#pragma unroll
        for (int e = 0; e < NE; e++) g[e] *= inv;

        int i1 = 0; float g1 = g[0];
#pragma unroll
        for (int e = 1; e < NE; e++) if (g[e] > g1) { g1 = g[e]; i1 = e; }
        int i2 = -1; float g2 = -1.0f;
#pragma unroll
        for (int e = 0; e < NE; e++)
            if (e != i1 && g[e] > g2) { g2 = g[e]; i2 = e; }

        float t  = expf((g2 - g1) * 0.5f);
        float d  = 1.0f / (1.0f + t);
        float w1 = d, w2 = t * d;

        int p1 = atomicAdd(&g_cnt[i1], 1);
        g_ptok[i1 * SEG + p1] = n;
        g_tpos[n * 2] = i1 * SEG + p1; g_tw[n * 2] = w1;
        int p2 = atomicAdd(&g_cnt[i2], 1);
        g_ptok[i2 * SEG + p2] = n;
        g_tpos[n * 2 + 1] = i2 * SEG + p2; g_tw[n * 2 + 1] = w2;
    }
}

// ---------------------------------------------------------------------------
// bf16x3 HMMA mainloop (R11-validated, verbatim).
// ---------------------------------------------------------------------------
#define GEMM_MAINLOOP(LDB, NCH)                                                \
    const int wid = tid >> 5, lane = tid & 31;                                 \
    const int wm = wid & 3, wn = wid >> 2;                                     \
    const int g = lane >> 2, tt = lane & 3;                                    \
    const int akh = (tid & 1) * 16;                                            \
    const int bkr = tid >> 3, bng = (tid & 7) * 16;                            \
    char* a_st = smem + OFF_AHI + (tid >> 1) * 80 + akh * 2;                   \
    char* b_st = smem + OFF_BHI + bkr * 272 + bng * 2;                         \
    const float* bsrc0 = W + (size_t)bkr * (LDB) + n0 + bng;                   \
    const uint32_t a_lm = smem_base + OFF_AHI +                                \
        (uint32_t)((wm * 32 + (lane & 15)) * 80 + (lane >> 4) * 16);           \
    const uint32_t b_lm = smem_base + OFF_BHI +                                \
        (uint32_t)(((lane & 7) + ((lane >> 3) & 1) * 8) * 272                  \
                   + (lane >> 4) * 16 + wn * 128);                             \
    float acc[2][8][4];                                                        \
    _Pragma("unroll")                                                          \
    for (int i = 0; i < 2; i++)                                                \
        _Pragma("unroll")                                                      \
        for (int j = 0; j < 8; j++)                                            \
            _Pragma("unroll")                                                  \
            for (int q = 0; q < 4; q++) acc[i][j][q] = 0.0f;                   \
    float4 pa[4], pb[4];                                                       \
    _Pragma("unroll")                                                          \
    for (int m = 0; m < 4; m++) {                                              \
        pa[m] = *(const float4*)(aptr + akh + m * 4);                          \
        pb[m] = *(const float4*)(bsrc0 + m * 4);                               \
    }                                                                          \
    for (int c = 0; c < (NCH); c++) {                                          \
        const uint32_t boff = (uint32_t)(c & 1) * SBUF;                        \
        uint32_t hw[8], lw[8];                                                 \
        SPLIT2(hw[0], lw[0], pa[0].x, pa[0].y);                                \
        SPLIT2(hw[1], lw[1], pa[0].z, pa[0].w);                                \
        SPLIT2(hw[2], lw[2], pa[1].x, pa[1].y);                                \
        SPLIT2(hw[3], lw[3], pa[1].z, pa[1].w);                                \
        SPLIT2(hw[4], lw[4], pa[2].x, pa[2].y);                                \
        SPLIT2(hw[5], lw[5], pa[2].z, pa[2].w);                                \
        SPLIT2(hw[6], lw[6], pa[3].x, pa[3].y);                                \
        SPLIT2(hw[7], lw[7], pa[3].z, pa[3].w);                                \
        *(uint4*)(a_st + boff)      = make_uint4(hw[0],hw[1],hw[2],hw[3]);     \
        *(uint4*)(a_st + boff + 16) = make_uint4(hw[4],hw[5],hw[6],hw[7]);     \
        *(uint4*)(a_st + boff + A_ARR)      = make_uint4(lw[0],lw[1],lw[2],lw[3]); \
        *(uint4*)(a_st + boff + A_ARR + 16) = make_uint4(lw[4],lw[5],lw[6],lw[7]); \
        SPLIT2(hw[0], lw[0], pb[0].x, pb[0].y);                                \
        SPLIT2(hw[1], lw[1], pb[0].z, pb[0].w);                                \
        SPLIT2(hw[2], lw[2], pb[1].x, pb[1].y);                                \
        SPLIT2(hw[3], lw[3], pb[1].z, pb[1].w);                                \
        SPLIT2(hw[4], lw[4], pb[2].x, pb[2].y);                                \
        SPLIT2(hw[5], lw[5], pb[2].z, pb[2].w);                                \
        SPLIT2(hw[6], lw[6], pb[3].x, pb[3].y);                                \
        SPLIT2(hw[7], lw[7], pb[3].z, pb[3].w);                                \
        *(uint4*)(b_st + boff)      = make_uint4(hw[0],hw[1],hw[2],hw[3]);     \
        *(uint4*)(b_st + boff + 16) = make_uint4(hw[4],hw[5],hw[6],hw[7]);     \
        *(uint4*)(b_st + boff + B_ARR)      = make_uint4(lw[0],lw[1],lw[2],lw[3]); \
        *(uint4*)(b_st + boff + B_ARR + 16) = make_uint4(lw[4],lw[5],lw[6],lw[7]); \
        __syncthreads();                                                       \
        if (c + 1 < (NCH)) {                                                   \
            const float* asrc = aptr + (c + 1) * KC + akh;                     \
            const float* bsrc = bsrc0 + (size_t)(c + 1) * KC * (LDB);          \
            _Pragma("unroll")                                                  \
            for (int m = 0; m < 4; m++) {                                      \
                pa[m] = *(const float4*)(asrc + m * 4);                        \
                pb[m] = *(const float4*)(bsrc + m * 4);                        \
            }                                                                  \
        }                                                                      \
        _Pragma("unroll")                                                      \
        for (int slab = 0; slab < 2; slab++) {                                 \
            uint32_t ah[2][4], al[2][4];                                       \
            _Pragma("unroll")                                                  \
            for (int i = 0; i < 2; i++) {                                      \
                uint32_t aa = a_lm + boff + (uint32_t)(i * 1280 + slab * 32);  \
                LDMX4(ah[i][0], ah[i][1], ah[i][2], ah[i][3], aa);             \
                LDMX4(al[i][0], al[i][1], al[i][2], al[i][3], aa + A_ARR);     \
            }                                                                  \
            _Pragma("unroll")                                                  \
            for (int jp = 0; jp < 4; jp++) {                                   \
                uint32_t bh[4], bl[4];                                         \
                uint32_t ba = b_lm + boff + (uint32_t)(slab * 4352 + jp * 32); \
                LDMX4T(bh[0], bh[1], bh[2], bh[3], ba);                        \
                LDMX4T(bl[0], bl[1], bl[2], bl[3], ba + B_ARR);                \
                _Pragma("unroll")                                              \
                for (int i = 0; i < 2; i++) {                                  \
                    mma_bf16(acc[i][2*jp],     ah[i], bh);                     \
                    mma_bf16(acc[i][2*jp],     al[i], bh);                     \
                    mma_bf16(acc[i][2*jp],     ah[i], bl);                     \
                    mma_bf16(acc[i][2*jp + 1], ah[i], bh + 2);                 \
                    mma_bf16(acc[i][2*jp + 1], al[i], bh + 2);                 \
                    mma_bf16(acc[i][2*jp + 1], ah[i], bl + 2);                 \
                }                                                              \
            }                                                                  \
        }                                                                      \
    }

// ---------------------------------------------------------------------------
// 3) grouped GEMM1: h = silu(gather(x) @ W1 + b1). grid (IDIM/128=32, 144)
// ---------------------------------------------------------------------------
__global__ void __launch_bounds__(256)
gemm1_k(const float* __restrict__ x,  const float* __restrict__ ew1,
        const float* __restrict__ eb1, const float* __restrict__ sw1,
        const float* __restrict__ sb1) {
    extern __shared__ char smem[];
    const int t = blockIdx.y, n0 = blockIdx.x * 128, tid = threadIdx.x;
    int* s_tok = (int*)(smem + OFF_TOK);

    const float* W; const float* bias;
    if (t < 128) {
        int e = t >> 4;
        int cnt = g_cnt[e];
        int lr0 = (t & 15) * 128;
        if (lr0 >= cnt) return;
        W = ew1 + (size_t)e * CDIM * IDIM;
        bias = eb1 + (size_t)e * IDIM;
        if (tid < 128) {
            int lr = lr0 + tid;
            s_tok[tid] = (lr < cnt) ? g_ptok[e * SEG + lr] : 0;
        }
    } else {
        W = sw1; bias = sb1;
        if (tid < 128) s_tok[tid] = (t - 128) * 128 + tid;
    }
    __syncthreads();

    uint32_t smem_base = smem_u32(smem);
    const float* aptr = x + (size_t)s_tok[tid >> 1] * CDIM;

    GEMM_MAINLOOP(IDIM, CDIM / KC)

#pragma unroll
    for (int i = 0; i < 2; i++)
#pragma unroll
        for (int j = 0; j < 8; j++) {
            const int row0 = t * 128 + wm * 32 + i * 16 + g;
            const int col = n0 + wn * 64 + j * 8 + 2 * tt;
            float b0 = bias[col], b1 = bias[col + 1];
            float v0 = acc[i][j][0] + b0, v1 = acc[i][j][1] + b1;
            float v2 = acc[i][j][2] + b0, v3 = acc[i][j][3] + b1;
            float2 lo, hi;
            lo.x = v0 / (1.0f + __expf(-v0)); lo.y = v1 / (1.0f + __expf(-v1));
            hi.x = v2 / (1.0f + __expf(-v2)); hi.y = v3 / (1.0f + __expf(-v3));
            *(float2*)(g_h + (size_t)row0 * IDIM + col) = lo;
            *(float2*)(g_h + (size_t)(row0 + 8) * IDIM + col) = hi;
        }
}

// ---------------------------------------------------------------------------
// 4) grouped GEMM2: eo = h @ W2 + b2. grid (CDIM/128=8, 144). K=4096
// ---------------------------------------------------------------------------
__global__ void __launch_bounds__(256)
gemm2_k(const float* __restrict__ ew2, const float* __restrict__ eb2,
        const float* __restrict__ sw2, const float* __restrict__ sb2) {
    extern __shared__ char smem[];
    const int t = blockIdx.y, n0 = blockIdx.x * 128, tid = threadIdx.x;

    const float* W; const float* bias;
    if (t < 128) {
        int e = t >> 4;
        if ((t & 15) * 128 >= g_cnt[e]) return;
        W = ew2 + (size_t)e * IDIM * CDIM;
        bias = eb2 + (size_t)e * CDIM;
    } else {
        W = sw2; bias = sb2;
    }
    __syncthreads();

    uint32_t smem_base = smem_u32(smem);
    const float* aptr = g_h + (size_t)(t * 128 + (tid >> 1)) * IDIM;

    GEMM_MAINLOOP(CDIM, IDIM / KC)

#pragma unroll
    for (int i = 0; i < 2; i++)
#pragma unroll
        for (int j = 0; j < 8; j++) {
            const int row0 = t * 128 + wm * 32 + i * 16 + g;
            const int col = n0 + wn * 64 + j * 8 + 2 * tt;
            float b0 = bias[col], b1 = bias[col + 1];
            float2 lo, hi;
            lo.x = acc[i][j][0] + b0; lo.y = acc[i][j][1] + b1;
            hi.x = acc[i][j][2] + b0; hi.y = acc[i][j][3] + b1;
            *(float2*)(g_eo + (size_t)row0 * CDIM + col) = lo;
            *(float2*)(g_eo + (size_t)(row0 + 8) * CDIM + col) = hi;
        }
}

// ---------------------------------------------------------------------------
// 5) combine: out[n] = eo[shared_n] + w0*eo[pos0] + w1*eo[pos1]
// ---------------------------------------------------------------------------
__global__ void combine_kernel(float* __restrict__ out) {
    int gid = blockIdx.x * 256 + threadIdx.x;
    int n = gid >> 8, c4 = gid & 255;
    const float4* eo = (const float4*)g_eo;
    float4 o = eo[(size_t)(R_EXP + n) * (CDIM / 4) + c4];
    int   p0 = g_tpos[n * 2],     p1 = g_tpos[n * 2 + 1];
    float w0 = g_tw[n * 2],       w1 = g_tw[n * 2 + 1];
    float4 a = eo[(size_t)p0 * (CDIM / 4) + c4];
    float4 b = eo[(size_t)p1 * (CDIM / 4) + c4];
    o.x += w0 * a.x + w1 * b.x;
    o.y += w0 * a.y + w1 * b.y;
    o.z += w0 * a.z + w1 * b.z;
    o.w += w0 * a.w + w1 * b.w;
    ((float4*)out)[gid] = o;
}

// ---------------------------------------------------------------------------
extern "C" void kernel_launch(void* const* d_in, const int* in_sizes, int n_in,
                              void* d_out, int out_size) {
    const float* x   = (const float*)d_in[0];
    const float* rw1 = (const float*)d_in[1];
    const float* rb1 = (const float*)d_in[2];
    const float* rw2 = (const float*)d_in[3];
    const float* rb2 = (const float*)d_in[4];
    const float* ew1 = (const float*)d_in[5];
    const float* eb1 = (const float*)d_in[6];
    const float* ew2 = (const float*)d_in[7];
    const float* eb2 = (const float*)d_in[8];
    const float* sw1 = (const float*)d_in[9];
    const float* sb1 = (const float*)d_in[10];
    const float* sw2 = (const float*)d_in[11];
    const float* sb2 = (const float*)d_in[12];
    float* out = (float*)d_out;

    static bool attr_done = false;
    if (!attr_done) {
        cudaFuncSetAttribute(gemm1_k, cudaFuncAttributeMaxDynamicSharedMemorySize, SMEM_TOTAL);
        cudaFuncSetAttribute(gemm2_k, cudaFuncAttributeMaxDynamicSharedMemorySize, SMEM_TOTAL);
        attr_done = true;
    }

    init_kernel<<<1, 32>>>();
    router_gemm<<<dim3(2, 16, RKS), 256>>>(x, rw1);
    sum_relu_kernel<<<N_TOK * RH / 4 / 256, 256>>>(rb1);
    route_kernel<<<256, 256>>>(rw2, rb2);
    gemm1_k<<<dim3(IDIM / 128, MT_TOT), 256, SMEM_TOTAL>>>(x, ew1, eb1, sw1, sb1);
    gemm2_k<<<dim3(CDIM / 128, MT_TOT), 256, SMEM_TOTAL>>>(ew2, eb2, sw2, sb2);
    combine_kernel<<<N_TOK * CDIM / 4 / 256, 256>>>(out);
}

// round 14
// speedup vs baseline: 1.4710x; 1.2019x over previous
#include <cuda_runtime.h>
#include <math.h>
#include <stdint.h>

// Problem dims
#define N_TOK 2048
#define CDIM  1024
#define RH    256
#define NE    8
#define IDIM  4096
#define SEG   2048
#define R_EXP (NE*SEG)          // 16384
#define R_TOT (R_EXP + N_TOK)   // 18432
#define MT_TOT (R_TOT/128)      // 144 row tiles
#define KC 32                   // K chunk
#define RKS 8                   // router K-split

// SMEM layout (bytes). Per buffer: A[128][40]fp16 (80B rows), B[32][136]fp16 (272B rows)
#define OFF_TOK  64
#define OFF_A    1024
#define A_ARR    10240                  // 128*80
#define OFF_B    (OFF_A + A_ARR)        // 11264
#define B_ARR    8704                   // 32*272
#define SBUF     (A_ARR + B_ARR)        // 18944 (one buffer)
#define SMEM_TOTAL (1024 + 2*SBUF)      // 38912

// Scratch
__device__ float g_y1p[(size_t)RKS * N_TOK * RH]; // router split-K partials
__device__ float g_y1[N_TOK * RH];                // router hidden (relu'd)
__device__ float g_h [(size_t)R_TOT * IDIM];      // silu(x@W1+b1)
__device__ float g_eo[(size_t)R_TOT * CDIM];      // h@W2+b2 per row
__device__ int   g_cnt[NE];
__device__ int   g_ptok[R_EXP];
__device__ int   g_tpos[N_TOK * 2];
__device__ float g_tw  [N_TOK * 2];

// ---------------------------------------------------------------------------
// helpers (all legal on base sm_103 target)
// ---------------------------------------------------------------------------
__device__ __forceinline__ void mma_fp16(float* d, const uint32_t* a, const uint32_t* b) {
    asm volatile(
        "mma.sync.aligned.m16n8k16.row.col.f32.f16.f16.f32 "
        "{%0,%1,%2,%3},{%4,%5,%6,%7},{%8,%9},{%0,%1,%2,%3};\n"
        : "+f"(d[0]), "+f"(d[1]), "+f"(d[2]), "+f"(d[3])
        : "r"(a[0]), "r"(a[1]), "r"(a[2]), "r"(a[3]), "r"(b[0]), "r"(b[1]));
}
#define LDMX4(r0,r1,r2,r3,addr) \
    asm volatile("ldmatrix.sync.aligned.m8n8.x4.shared.b16 {%0,%1,%2,%3}, [%4];" \
        : "=r"(r0),"=r"(r1),"=r"(r2),"=r"(r3) : "r"(addr))
#define LDMX4T(r0,r1,r2,r3,addr) \
    asm volatile("ldmatrix.sync.aligned.m8n8.x4.trans.shared.b16 {%0,%1,%2,%3}, [%4];" \
        : "=r"(r0),"=r"(r1),"=r"(r2),"=r"(r3) : "r"(addr))

// fp32 pair -> packed fp16x2 word (v0 in low half)
#define CVT2(hw, v0, v1) \
    asm("cvt.rn.f16x2.f32 %0, %1, %2;" : "=r"(hw) : "f"(v1), "f"(v0))

__device__ __forceinline__ uint32_t smem_u32(const void* p) {
    uint32_t a;
    asm("{ .reg .u64 t; cvta.to.shared.u64 t, %1; cvt.u32.u64 %0, t; }"
        : "=r"(a) : "l"(p));
    return a;
}

// ---------------------------------------------------------------------------
// 0) init counters
// ---------------------------------------------------------------------------
__global__ void init_kernel() {
    if (threadIdx.x < NE) g_cnt[threadIdx.x] = 0;
}

// ---------------------------------------------------------------------------
// 1) router GEMM split-K=8 (deterministic partials): y1p[s] = x[:,ks] @ rw1[ks,:]
// ---------------------------------------------------------------------------
__global__ void __launch_bounds__(256, 2)
router_gemm(const float* __restrict__ x, const float* __restrict__ rw1) {
    __shared__ float As[8][128];
    __shared__ float Bs[8][128];
    const int tid = threadIdx.x;
    const int m0 = blockIdx.y * 128;
    const int n0 = blockIdx.x * 128;
    const int ks = blockIdx.z * (CDIM / RKS);

    const int ar = tid >> 1, kh = (tid & 1) * 4;
    const int kb = tid >> 5, bn = (tid & 31) * 4;
    const float* arow = x + (size_t)(m0 + ar) * CDIM + ks;
    const float* bptr = rw1 + (size_t)(ks + kb) * RH + n0 + bn;
    const int tm = (tid >> 4) * 8, tn = (tid & 15) * 8;

    float acc[8][8];
#pragma unroll
    for (int i = 0; i < 8; i++)
#pragma unroll
        for (int j = 0; j < 8; j++) acc[i][j] = 0.0f;

    for (int k0 = 0; k0 < CDIM / RKS; k0 += 8) {
        float4 av = *(const float4*)(arow + k0 + kh);
        As[kh + 0][ar] = av.x; As[kh + 1][ar] = av.y;
        As[kh + 2][ar] = av.z; As[kh + 3][ar] = av.w;
        *(float4*)&Bs[kb][bn] = *(const float4*)(bptr + (size_t)k0 * RH);
        __syncthreads();
#pragma unroll
        for (int kk = 0; kk < 8; kk++) {
            float a[8], b[8];
#pragma unroll
            for (int i = 0; i < 8; i++) a[i] = As[kk][tm + i];
#pragma unroll
            for (int j = 0; j < 8; j++) b[j] = Bs[kk][tn + j];
#pragma unroll
            for (int i = 0; i < 8; i++)
#pragma unroll
                for (int j = 0; j < 8; j++) acc[i][j] += a[i] * b[j];
        }
        __syncthreads();
    }
#pragma unroll
    for (int i = 0; i < 8; i++) {
        float* dst = g_y1p + ((size_t)blockIdx.z * N_TOK + m0 + tm + i) * RH + n0 + tn;
#pragma unroll
        for (int j = 0; j < 8; j++) dst[j] = acc[i][j];
    }
}

// ---------------------------------------------------------------------------
// 1b) sum partials + rb1 + relu -> g_y1. grid 512 x 256, float4 per thread.
// ---------------------------------------------------------------------------
__global__ void sum_relu_kernel(const float* __restrict__ rb1) {
    int i4 = blockIdx.x * 256 + threadIdx.x;
    const float4* p = (const float4*)g_y1p;
    float4 a = p[i4];
#pragma unroll
    for (int s = 1; s < RKS; s++) {
        float4 v = p[(size_t)s * (N_TOK * RH / 4) + i4];
        a.x += v.x; a.y += v.y; a.z += v.z; a.w += v.w;
    }
    float4 b = ((const float4*)rb1)[i4 & (RH / 4 - 1)];
    a.x = fmaxf(a.x + b.x, 0.0f);
    a.y = fmaxf(a.y + b.y, 0.0f);
    a.z = fmaxf(a.z + b.z, 0.0f);
    a.w = fmaxf(a.w + b.w, 0.0f);
    ((float4*)g_y1)[i4] = a;
}

// ---------------------------------------------------------------------------
// 2) routing (warp-per-token): logits -> softmax -> top2 -> scatter
// ---------------------------------------------------------------------------
__global__ void route_kernel(const float* __restrict__ rw2,
                             const float* __restrict__ rb2) {
    __shared__ float s_w[RH * NE];
    __shared__ float s_b[NE];
    const int tid = threadIdx.x;
    for (int i = tid; i < RH * NE; i += 256) s_w[i] = rw2[i];
    if (tid < NE) s_b[tid] = rb2[tid];
    __syncthreads();

    const int n = blockIdx.x * 8 + (tid >> 5);
    const int lane = tid & 31;
    const float* y = g_y1 + (size_t)n * RH;

    float acc[NE];
#pragma unroll
    for (int e = 0; e < NE; e++) acc[e] = 0.0f;
#pragma unroll
    for (int cb = 0; cb < RH; cb += 32) {
        float v = y[cb + lane];
        const float* wrow = s_w + (cb + lane) * NE;
#pragma unroll
        for (int e = 0; e < NE; e++) acc[e] += v * wrow[e];
    }
#pragma unroll
    for (int off = 16; off > 0; off >>= 1)
#pragma unroll
        for (int e = 0; e < NE; e++)
            acc[e] += __shfl_down_sync(0xffffffff, acc[e], off);

    if (lane == 0) {
#pragma unroll
        for (int e = 0; e < NE; e++) acc[e] += s_b[e];
        float m = acc[0];
#pragma unroll
        for (int e = 1; e < NE; e++) m = fmaxf(m, acc[e]);
        float s = 0.0f, g[NE];
#pragma unroll
        for (int e = 0; e < NE; e++) { g[e] = expf(acc[e] - m); s += g[e]; }
        float inv = 1.0f / s;
#pragma unroll
        for (int e = 0; e < NE; e++) g[e] *= inv;

        int i1 = 0; float g1 = g[0];
#pragma unroll
        for (int e = 1; e < NE; e++) if (g[e] > g1) { g1 = g[e]; i1 = e; }
        int i2 = -1; float g2 = -1.0f;
#pragma unroll
        for (int e = 0; e < NE; e++)
            if (e != i1 && g[e] > g2) { g2 = g[e]; i2 = e; }

        float t  = expf((g2 - g1) * 0.5f);
        float d  = 1.0f / (1.0f + t);
        float w1 = d, w2 = t * d;

        int p1 = atomicAdd(&g_cnt[i1], 1);
        g_ptok[i1 * SEG + p1] = n;
        g_tpos[n * 2] = i1 * SEG + p1; g_tw[n * 2] = w1;
        int p2 = atomicAdd(&g_cnt[i2], 1);
        g_ptok[i2 * SEG + p2] = n;
        g_tpos[n * 2 + 1] = i2 * SEG + p2; g_tw[n * 2 + 1] = w2;
    }
}

// ---------------------------------------------------------------------------
// fp16 single-term HMMA mainloop (R11 structure, lo-arrays/residuals removed).
// A[128 x KC] from aptr (per-thread row base), B[128n x KC] from W (k-major,
// ld = LDB). SMEM: A [m][k] fp16 80B rows; B [k][n] fp16 272B rows.
// Double-buffered, 1 sync/chunk, LDG prefetch.
// ---------------------------------------------------------------------------
#define GEMM_MAINLOOP(LDB, NCH)                                                \
    const int wid = tid >> 5, lane = tid & 31;                                 \
    const int wm = wid & 3, wn = wid >> 2;                                     \
    const int g = lane >> 2, tt = lane & 3;                                    \
    const int akh = (tid & 1) * 16;                                            \
    const int bkr = tid >> 3, bng = (tid & 7) * 16;                            \
    char* a_st = smem + OFF_A + (tid >> 1) * 80 + akh * 2;                     \
    char* b_st = smem + OFF_B + bkr * 272 + bng * 2;                           \
    const float* bsrc0 = W + (size_t)bkr * (LDB) + n0 + bng;                   \
    const uint32_t a_lm = smem_base + OFF_A +                                  \
        (uint32_t)((wm * 32 + (lane & 15)) * 80 + (lane >> 4) * 16);           \
    const uint32_t b_lm = smem_base + OFF_B +                                  \
        (uint32_t)(((lane & 7) + ((lane >> 3) & 1) * 8) * 272                  \
                   + (lane >> 4) * 16 + wn * 128);                             \
    float acc[2][8][4];                                                        \
    _Pragma("unroll")                                                          \
    for (int i = 0; i < 2; i++)                                                \
        _Pragma("unroll")                                                      \
        for (int j = 0; j < 8; j++)                                            \
            _Pragma("unroll")                                                  \
            for (int q = 0; q < 4; q++) acc[i][j][q] = 0.0f;                   \
    float4 pa[4], pb[4];                                                       \
    _Pragma("unroll")                                                          \
    for (int m = 0; m < 4; m++) {                                              \
        pa[m] = *(const float4*)(aptr + akh + m * 4);                          \
        pb[m] = *(const float4*)(bsrc0 + m * 4);                               \
    }                                                                          \
    for (int c = 0; c < (NCH); c++) {                                          \
        const uint32_t boff = (uint32_t)(c & 1) * SBUF;                        \
        uint32_t hw[8];                                                        \
        CVT2(hw[0], pa[0].x, pa[0].y);                                         \
        CVT2(hw[1], pa[0].z, pa[0].w);                                         \
        CVT2(hw[2], pa[1].x, pa[1].y);                                         \
        CVT2(hw[3], pa[1].z, pa[1].w);                                         \
        CVT2(hw[4], pa[2].x, pa[2].y);                                         \
        CVT2(hw[5], pa[2].z, pa[2].w);                                         \
        CVT2(hw[6], pa[3].x, pa[3].y);                                         \
        CVT2(hw[7], pa[3].z, pa[3].w);                                         \
        *(uint4*)(a_st + boff)      = make_uint4(hw[0],hw[1],hw[2],hw[3]);     \
        *(uint4*)(a_st + boff + 16) = make_uint4(hw[4],hw[5],hw[6],hw[7]);     \
        CVT2(hw[0], pb[0].x, pb[0].y);                                         \
        CVT2(hw[1], pb[0].z, pb[0].w);                                         \
        CVT2(hw[2], pb[1].x, pb[1].y);                                         \
        CVT2(hw[3], pb[1].z, pb[1].w);                                         \
        CVT2(hw[4], pb[2].x, pb[2].y);                                         \
        CVT2(hw[5], pb[2].z, pb[2].w);                                         \
        CVT2(hw[6], pb[3].x, pb[3].y);                                         \
        CVT2(hw[7], pb[3].z, pb[3].w);                                         \
        *(uint4*)(b_st + boff)      = make_uint4(hw[0],hw[1],hw[2],hw[3]);     \
        *(uint4*)(b_st + boff + 16) = make_uint4(hw[4],hw[5],hw[6],hw[7]);     \
        __syncthreads();                                                       \
        if (c + 1 < (NCH)) {                                                   \
            const float* asrc = aptr + (c + 1) * KC + akh;                     \
            const float* bsrc = bsrc0 + (size_t)(c + 1) * KC * (LDB);          \
            _Pragma("unroll")                                                  \
            for (int m = 0; m < 4; m++) {                                      \
                pa[m] = *(const float4*)(asrc + m * 4);                        \
                pb[m] = *(const float4*)(bsrc + m * 4);                        \
            }                                                                  \
        }                                                                      \
        _Pragma("unroll")                                                      \
        for (int slab = 0; slab < 2; slab++) {                                 \
            uint32_t ah[2][4];                                                 \
            _Pragma("unroll")                                                  \
            for (int i = 0; i < 2; i++) {                                      \
                uint32_t aa = a_lm + boff + (uint32_t)(i * 1280 + slab * 32);  \
                LDMX4(ah[i][0], ah[i][1], ah[i][2], ah[i][3], aa);             \
            }                                                                  \
            _Pragma("unroll")                                                  \
            for (int jp = 0; jp < 4; jp++) {                                   \
                uint32_t bh[4];                                                \
                uint32_t ba = b_lm + boff + (uint32_t)(slab * 4352 + jp * 32); \
                LDMX4T(bh[0], bh[1], bh[2], bh[3], ba);                        \
                _Pragma("unroll")                                              \
                for (int i = 0; i < 2; i++) {                                  \
                    mma_fp16(acc[i][2*jp],     ah[i], bh);                     \
                    mma_fp16(acc[i][2*jp + 1], ah[i], bh + 2);                 \
                }                                                              \
            }                                                                  \
        }                                                                      \
    }

// ---------------------------------------------------------------------------
// 3) grouped GEMM1: h = silu(gather(x) @ W1 + b1). grid (IDIM/128=32, 144)
// ---------------------------------------------------------------------------
__global__ void __launch_bounds__(256)
gemm1_k(const float* __restrict__ x,  const float* __restrict__ ew1,
        const float* __restrict__ eb1, const float* __restrict__ sw1,
        const float* __restrict__ sb1) {
    extern __shared__ char smem[];
    const int t = blockIdx.y, n0 = blockIdx.x * 128, tid = threadIdx.x;
    int* s_tok = (int*)(smem + OFF_TOK);

    const float* W; const float* bias;
    if (t < 128) {
        int e = t >> 4;
        int cnt = g_cnt[e];
        int lr0 = (t & 15) * 128;
        if (lr0 >= cnt) return;
        W = ew1 + (size_t)e * CDIM * IDIM;
        bias = eb1 + (size_t)e * IDIM;
        if (tid < 128) {
            int lr = lr0 + tid;
            s_tok[tid] = (lr < cnt) ? g_ptok[e * SEG + lr] : 0;
        }
    } else {
        W = sw1; bias = sb1;
        if (tid < 128) s_tok[tid] = (t - 128) * 128 + tid;
    }
    __syncthreads();

    uint32_t smem_base = smem_u32(smem);
    const float* aptr = x + (size_t)s_tok[tid >> 1] * CDIM;

    GEMM_MAINLOOP(IDIM, CDIM / KC)

#pragma unroll
    for (int i = 0; i < 2; i++)
#pragma unroll
        for (int j = 0; j < 8; j++) {
            const int row0 = t * 128 + wm * 32 + i * 16 + g;
            const int col = n0 + wn * 64 + j * 8 + 2 * tt;
            float b0 = bias[col], b1 = bias[col + 1];
            float v0 = acc[i][j][0] + b0, v1 = acc[i][j][1] + b1;
            float v2 = acc[i][j][2] + b0, v3 = acc[i][j][3] + b1;
            float2 lo, hi;
            lo.x = v0 / (1.0f + __expf(-v0)); lo.y = v1 / (1.0f + __expf(-v1));
            hi.x = v2 / (1.0f + __expf(-v2)); hi.y = v3 / (1.0f + __expf(-v3));
            *(float2*)(g_h + (size_t)row0 * IDIM + col) = lo;
            *(float2*)(g_h + (size_t)(row0 + 8) * IDIM + col) = hi;
        }
}

// ---------------------------------------------------------------------------
// 4) grouped GEMM2: eo = h @ W2 + b2. grid (CDIM/128=8, 144). K=4096
// ---------------------------------------------------------------------------
__global__ void __launch_bounds__(256)
gemm2_k(const float* __restrict__ ew2, const float* __restrict__ eb2,
        const float* __restrict__ sw2, const float* __restrict__ sb2) {
    extern __shared__ char smem[];
    const int t = blockIdx.y, n0 = blockIdx.x * 128, tid = threadIdx.x;

    const float* W; const float* bias;
    if (t < 128) {
        int e = t >> 4;
        if ((t & 15) * 128 >= g_cnt[e]) return;
        W = ew2 + (size_t)e * IDIM * CDIM;
        bias = eb2 + (size_t)e * CDIM;
    } else {
        W = sw2; bias = sb2;
    }
    __syncthreads();

    uint32_t smem_base = smem_u32(smem);
    const float* aptr = g_h + (size_t)(t * 128 + (tid >> 1)) * IDIM;

    GEMM_MAINLOOP(CDIM, IDIM / KC)

#pragma unroll
    for (int i = 0; i < 2; i++)
#pragma unroll
        for (int j = 0; j < 8; j++) {
            const int row0 = t * 128 + wm * 32 + i * 16 + g;
            const int col = n0 + wn * 64 + j * 8 + 2 * tt;
            float b0 = bias[col], b1 = bias[col + 1];
            float2 lo, hi;
            lo.x = acc[i][j][0] + b0; lo.y = acc[i][j][1] + b1;
            hi.x = acc[i][j][2] + b0; hi.y = acc[i][j][3] + b1;
            *(float2*)(g_eo + (size_t)row0 * CDIM + col) = lo;
            *(float2*)(g_eo + (size_t)(row0 + 8) * CDIM + col) = hi;
        }
}

// ---------------------------------------------------------------------------
// 5) combine: out[n] = eo[shared_n] + w0*eo[pos0] + w1*eo[pos1]
// ---------------------------------------------------------------------------
__global__ void combine_kernel(float* __restrict__ out) {
    int gid = blockIdx.x * 256 + threadIdx.x;
    int n = gid >> 8, c4 = gid & 255;
    const float4* eo = (const float4*)g_eo;
    float4 o = eo[(size_t)(R_EXP + n) * (CDIM / 4) + c4];
    int   p0 = g_tpos[n * 2],     p1 = g_tpos[n * 2 + 1];
    float w0 = g_tw[n * 2],       w1 = g_tw[n * 2 + 1];
    float4 a = eo[(size_t)p0 * (CDIM / 4) + c4];
    float4 b = eo[(size_t)p1 * (CDIM / 4) + c4];
    o.x += w0 * a.x + w1 * b.x;
    o.y += w0 * a.y + w1 * b.y;
    o.z += w0 * a.z + w1 * b.z;
    o.w += w0 * a.w + w1 * b.w;
    ((float4*)out)[gid] = o;
}

// ---------------------------------------------------------------------------
extern "C" void kernel_launch(void* const* d_in, const int* in_sizes, int n_in,
                              void* d_out, int out_size) {
    const float* x   = (const float*)d_in[0];
    const float* rw1 = (const float*)d_in[1];
    const float* rb1 = (const float*)d_in[2];
    const float* rw2 = (const float*)d_in[3];
    const float* rb2 = (const float*)d_in[4];
    const float* ew1 = (const float*)d_in[5];
    const float* eb1 = (const float*)d_in[6];
    const float* ew2 = (const float*)d_in[7];
    const float* eb2 = (const float*)d_in[8];
    const float* sw1 = (const float*)d_in[9];
    const float* sb1 = (const float*)d_in[10];
    const float* sw2 = (const float*)d_in[11];
    const float* sb2 = (const float*)d_in[12];
    float* out = (float*)d_out;

    static bool attr_done = false;
    if (!attr_done) {
        cudaFuncSetAttribute(gemm1_k, cudaFuncAttributeMaxDynamicSharedMemorySize, SMEM_TOTAL);
        cudaFuncSetAttribute(gemm2_k, cudaFuncAttributeMaxDynamicSharedMemorySize, SMEM_TOTAL);
        attr_done = true;
    }

    init_kernel<<<1, 32>>>();
    router_gemm<<<dim3(2, 16, RKS), 256>>>(x, rw1);
    sum_relu_kernel<<<N_TOK * RH / 4 / 256, 256>>>(rb1);
    route_kernel<<<256, 256>>>(rw2, rb2);
    gemm1_k<<<dim3(IDIM / 128, MT_TOT), 256, SMEM_TOTAL>>>(x, ew1, eb1, sw1, sb1);
    gemm2_k<<<dim3(CDIM / 128, MT_TOT), 256, SMEM_TOTAL>>>(ew2, eb2, sw2, sb2);
    combine_kernel<<<N_TOK * CDIM / 4 / 256, 256>>>(out);
}

// round 16
// speedup vs baseline: 2.3669x; 1.6090x over previous
#include <cuda_runtime.h>
#include <cuda_fp16.h>
#include <math.h>
#include <stdint.h>

// Problem dims
#define N_TOK 2048
#define CDIM  1024
#define RH    256
#define NE    8
#define IDIM  4096
#define SEG   2048
#define R_EXP (NE*SEG)          // 16384
#define R_TOT (R_EXP + N_TOK)   // 18432
#define MT_TOT (R_TOT/128)      // 144 row tiles
#define KC 32                   // K chunk
#define RKS 8                   // router K-split
#define WELEM ((size_t)CDIM*IDIM)   // 2^22 elems per expert matrix

// SMEM layout (bytes). Per buffer: A[128][40]fp16 (80B rows), B[32][136]fp16 (272B rows)
#define OFF_TOK  64
#define OFF_A    1024
#define A_ARR    10240                  // 128*80
#define OFF_B    (OFF_A + A_ARR)        // 11264
#define B_ARR    8704                   // 32*272
#define SBUF     (A_ARR + B_ARR)        // 18944 (one buffer)
#define SMEM_TOTAL (1024 + 2*SBUF)      // 38912

// Scratch
__device__ __half g_xh[(size_t)N_TOK * CDIM];     // x in fp16
__device__ __half g_w1h[9 * WELEM];               // W1 (+shared) fp16
__device__ __half g_w2h[9 * WELEM];               // W2 (+shared) fp16
__device__ __half g_h [(size_t)R_TOT * IDIM];     // silu(x@W1+b1), fp16
__device__ float  g_eo[(size_t)R_TOT * CDIM];     // h@W2+b2 per row
__device__ float  g_y1p[(size_t)RKS * N_TOK * RH];
__device__ float  g_y1[N_TOK * RH];
__device__ int    g_cnt[NE];
__device__ int    g_ptok[R_EXP];
__device__ int    g_tpos[N_TOK * 2];
__device__ float  g_tw  [N_TOK * 2];

// ---------------------------------------------------------------------------
// helpers (all legal on base sm_103 target)
// ---------------------------------------------------------------------------
__device__ __forceinline__ void mma_fp16(float* d, const uint32_t* a, const uint32_t* b) {
    asm volatile(
        "mma.sync.aligned.m16n8k16.row.col.f32.f16.f16.f32 "
        "{%0,%1,%2,%3},{%4,%5,%6,%7},{%8,%9},{%0,%1,%2,%3};\n"
        : "+f"(d[0]), "+f"(d[1]), "+f"(d[2]), "+f"(d[3])
        : "r"(a[0]), "r"(a[1]), "r"(a[2]), "r"(a[3]), "r"(b[0]), "r"(b[1]));
}
#define LDMX4(r0,r1,r2,r3,addr) \
    asm volatile("ldmatrix.sync.aligned.m8n8.x4.shared.b16 {%0,%1,%2,%3}, [%4];" \
        : "=r"(r0),"=r"(r1),"=r"(r2),"=r"(r3) : "r"(addr))
#define LDMX4T(r0,r1,r2,r3,addr) \
    asm volatile("ldmatrix.sync.aligned.m8n8.x4.trans.shared.b16 {%0,%1,%2,%3}, [%4];" \
        : "=r"(r0),"=r"(r1),"=r"(r2),"=r"(r3) : "r"(addr))

// fp32 pair -> packed fp16x2 word (v0 in low half)
#define CVT2(hw, v0, v1) \
    asm("cvt.rn.f16x2.f32 %0, %1, %2;" : "=r"(hw) : "f"(v1), "f"(v0))

__device__ __forceinline__ uint32_t smem_u32(const void* p) {
    uint32_t a;
    asm("{ .reg .u64 t; cvta.to.shared.u64 t, %1; cvt.u32.u64 %0, t; }"
        : "=r"(a) : "l"(p));
    return a;
}
#define CP16(dst, src) asm volatile("cp.async.ca.shared.global [%0], [%1], 16;"::"r"(dst),"l"(src))
#define CP_COMMIT()    asm volatile("cp.async.commit_group;")
#define CP_WAIT0()     asm volatile("cp.async.wait_group 0;")

// ---------------------------------------------------------------------------
// 0) init counters
// ---------------------------------------------------------------------------
__global__ void init_kernel() {
    if (threadIdx.x < NE) g_cnt[threadIdx.x] = 0;
}

// ---------------------------------------------------------------------------
// 0b) fp32 -> fp16 converts. Destination selected IN DEVICE CODE (passing a
// __device__ symbol from host passes the host shadow address — on GB300 with
// ATS that write silently lands in host memory; R15's bug).
// ---------------------------------------------------------------------------
__global__ void cvt_x_k(const float* __restrict__ x) {
    size_t i = ((size_t)blockIdx.x * 256 + threadIdx.x) * 4;
    float4 v = *(const float4*)(x + i);
    uint32_t h0, h1;
    CVT2(h0, v.x, v.y);
    CVT2(h1, v.z, v.w);
    *(uint2*)(g_xh + i) = make_uint2(h0, h1);
}

__global__ void cvt_w_k(const float* __restrict__ ew,
                        const float* __restrict__ sw, int which) {
    size_t i = ((size_t)blockIdx.x * 256 + threadIdx.x) * 4;
    size_t e = i >> 22, off = i & (WELEM - 1);
    float4 v = (e < 8) ? *(const float4*)(ew + e * WELEM + off)
                       : *(const float4*)(sw + off);
    uint32_t h0, h1;
    CVT2(h0, v.x, v.y);
    CVT2(h1, v.z, v.w);
    __half* dst = which ? g_w2h : g_w1h;
    *(uint2*)(dst + i) = make_uint2(h0, h1);
}

// ---------------------------------------------------------------------------
// 1) router GEMM split-K=8 (deterministic partials)
// ---------------------------------------------------------------------------
__global__ void __launch_bounds__(256, 2)
router_gemm(const float* __restrict__ x, const float* __restrict__ rw1) {
    __shared__ float As[8][128];
    __shared__ float Bs[8][128];
    const int tid = threadIdx.x;
    const int m0 = blockIdx.y * 128;
    const int n0 = blockIdx.x * 128;
    const int ks = blockIdx.z * (CDIM / RKS);

    const int ar = tid >> 1, kh = (tid & 1) * 4;
    const int kb = tid >> 5, bn = (tid & 31) * 4;
    const float* arow = x + (size_t)(m0 + ar) * CDIM + ks;
    const float* bptr = rw1 + (size_t)(ks + kb) * RH + n0 + bn;
    const int tm = (tid >> 4) * 8, tn = (tid & 15) * 8;

    float acc[8][8];
#pragma unroll
    for (int i = 0; i < 8; i++)
#pragma unroll
        for (int j = 0; j < 8; j++) acc[i][j] = 0.0f;

    for (int k0 = 0; k0 < CDIM / RKS; k0 += 8) {
        float4 av = *(const float4*)(arow + k0 + kh);
        As[kh + 0][ar] = av.x; As[kh + 1][ar] = av.y;
        As[kh + 2][ar] = av.z; As[kh + 3][ar] = av.w;
        *(float4*)&Bs[kb][bn] = *(const float4*)(bptr + (size_t)k0 * RH);
        __syncthreads();
#pragma unroll
        for (int kk = 0; kk < 8; kk++) {
            float a[8], b[8];
#pragma unroll
            for (int i = 0; i < 8; i++) a[i] = As[kk][tm + i];
#pragma unroll
            for (int j = 0; j < 8; j++) b[j] = Bs[kk][tn + j];
#pragma unroll
            for (int i = 0; i < 8; i++)
#pragma unroll
                for (int j = 0; j < 8; j++) acc[i][j] += a[i] * b[j];
        }
        __syncthreads();
    }
#pragma unroll
    for (int i = 0; i < 8; i++) {
        float* dst = g_y1p + ((size_t)blockIdx.z * N_TOK + m0 + tm + i) * RH + n0 + tn;
#pragma unroll
        for (int j = 0; j < 8; j++) dst[j] = acc[i][j];
    }
}

// ---------------------------------------------------------------------------
// 1b) sum partials + rb1 + relu -> g_y1
// ---------------------------------------------------------------------------
__global__ void sum_relu_kernel(const float* __restrict__ rb1) {
    int i4 = blockIdx.x * 256 + threadIdx.x;
    const float4* p = (const float4*)g_y1p;
    float4 a = p[i4];
#pragma unroll
    for (int s = 1; s < RKS; s++) {
        float4 v = p[(size_t)s * (N_TOK * RH / 4) + i4];
        a.x += v.x; a.y += v.y; a.z += v.z; a.w += v.w;
    }
    float4 b = ((const float4*)rb1)[i4 & (RH / 4 - 1)];
    a.x = fmaxf(a.x + b.x, 0.0f);
    a.y = fmaxf(a.y + b.y, 0.0f);
    a.z = fmaxf(a.z + b.z, 0.0f);
    a.w = fmaxf(a.w + b.w, 0.0f);
    ((float4*)g_y1)[i4] = a;
}

// ---------------------------------------------------------------------------
// 2) routing (warp-per-token)
// ---------------------------------------------------------------------------
__global__ void route_kernel(const float* __restrict__ rw2,
                             const float* __restrict__ rb2) {
    __shared__ float s_w[RH * NE];
    __shared__ float s_b[NE];
    const int tid = threadIdx.x;
    for (int i = tid; i < RH * NE; i += 256) s_w[i] = rw2[i];
    if (tid < NE) s_b[tid] = rb2[tid];
    __syncthreads();

    const int n = blockIdx.x * 8 + (tid >> 5);
    const int lane = tid & 31;
    const float* y = g_y1 + (size_t)n * RH;

    float acc[NE];
#pragma unroll
    for (int e = 0; e < NE; e++) acc[e] = 0.0f;
#pragma unroll
    for (int cb = 0; cb < RH; cb += 32) {
        float v = y[cb + lane];
        const float* wrow = s_w + (cb + lane) * NE;
#pragma unroll
        for (int e = 0; e < NE; e++) acc[e] += v * wrow[e];
    }
#pragma unroll
    for (int off = 16; off > 0; off >>= 1)
#pragma unroll
        for (int e = 0; e < NE; e++)
            acc[e] += __shfl_down_sync(0xffffffff, acc[e], off);

    if (lane == 0) {
#pragma unroll
        for (int e = 0; e < NE; e++) acc[e] += s_b[e];
        float m = acc[0];
#pragma unroll
        for (int e = 1; e < NE; e++) m = fmaxf(m, acc[e]);
        float s = 0.0f, g[NE];
#pragma unroll
        for (int e = 0; e < NE; e++) { g[e] = expf(acc[e] - m); s += g[e]; }
        float inv = 1.0f / s;
#pragma unroll
        for (int e = 0; e < NE; e++) g[e] *= inv;

        int i1 = 0; float g1 = g[0];
#pragma unroll
        for (int e = 1; e < NE; e++) if (g[e] > g1) { g1 = g[e]; i1 = e; }
        int i2 = -1; float g2 = -1.0f;
#pragma unroll
        for (int e = 0; e < NE; e++)
            if (e != i1 && g[e] > g2) { g2 = g[e]; i2 = e; }

        float t  = expf((g2 - g1) * 0.5f);
        float d  = 1.0f / (1.0f + t);
        float w1 = d, w2 = t * d;

        int p1 = atomicAdd(&g_cnt[i1], 1);
        g_ptok[i1 * SEG + p1] = n;
        g_tpos[n * 2] = i1 * SEG + p1; g_tw[n * 2] = w1;
        int p2 = atomicAdd(&g_cnt[i2], 1);
        g_ptok[i2 * SEG + p2] = n;
        g_tpos[n * 2 + 1] = i2 * SEG + p2; g_tw[n * 2 + 1] = w2;
    }
}

// ---------------------------------------------------------------------------
// fp16 HMMA mainloop, cp.async fills (no in-loop converts, no prefetch regs).
// ---------------------------------------------------------------------------
#define FILLC(cc) do {                                                         \
    uint32_t _bo = (uint32_t)((cc) & 1) * SBUF;                                \
    const char* _a = a_src + (size_t)(cc) * (KC * 2);                          \
    CP16(a_dst + _bo,      _a);  CP16(a_dst + _bo + 16, _a + 16);              \
    const char* _b = b_src + (size_t)(cc) * bstep;                             \
    CP16(b_dst + _bo,      _b);  CP16(b_dst + _bo + 16, _b + 16);              \
    CP_COMMIT();                                                               \
} while (0)

#define GEMM_MAINLOOP(LDB, NCH)                                                \
    const int wid = tid >> 5, lane = tid & 31;                                 \
    const int wm = wid & 3, wn = wid >> 2;                                     \
    const int g = lane >> 2, tt = lane & 3;                                    \
    const size_t bstep = (size_t)KC * (LDB) * 2;                               \
    const uint32_t a_dst = smem_base + OFF_A                                   \
        + (uint32_t)((tid >> 1) * 80 + (tid & 1) * 32);                        \
    const uint32_t b_dst = smem_base + OFF_B                                   \
        + (uint32_t)((tid >> 3) * 272 + (tid & 7) * 32);                       \
    const uint32_t a_lm = smem_base + OFF_A +                                  \
        (uint32_t)((wm * 32 + (lane & 15)) * 80 + (lane >> 4) * 16);           \
    const uint32_t b_lm = smem_base + OFF_B +                                  \
        (uint32_t)(((lane & 7) + ((lane >> 3) & 1) * 8) * 272                  \
                   + (lane >> 4) * 16 + wn * 128);                             \
    float acc[2][8][4];                                                        \
    _Pragma("unroll")                                                          \
    for (int i = 0; i < 2; i++)                                                \
        _Pragma("unroll")                                                      \
        for (int j = 0; j < 8; j++)                                            \
            _Pragma("unroll")                                                  \
            for (int q = 0; q < 4; q++) acc[i][j][q] = 0.0f;                   \
    FILLC(0);                                                                  \
    for (int c = 0; c < (NCH); c++) {                                          \
        const uint32_t boff = (uint32_t)(c & 1) * SBUF;                        \
        CP_WAIT0();                                                            \
        __syncthreads();                                                       \
        if (c + 1 < (NCH)) { FILLC(c + 1); }                                   \
        _Pragma("unroll")                                                      \
        for (int slab = 0; slab < 2; slab++) {                                 \
            uint32_t ah[2][4];                                                 \
            _Pragma("unroll")                                                  \
            for (int i = 0; i < 2; i++) {                                      \
                uint32_t aa = a_lm + boff + (uint32_t)(i * 1280 + slab * 32);  \
                LDMX4(ah[i][0], ah[i][1], ah[i][2], ah[i][3], aa);             \
            }                                                                  \
            _Pragma("unroll")                                                  \
            for (int jp = 0; jp < 4; jp++) {                                   \
                uint32_t bh[4];                                                \
                uint32_t ba = b_lm + boff + (uint32_t)(slab * 4352 + jp * 32); \
                LDMX4T(bh[0], bh[1], bh[2], bh[3], ba);                        \
                _Pragma("unroll")                                              \
                for (int i = 0; i < 2; i++) {                                  \
                    mma_fp16(acc[i][2*jp],     ah[i], bh);                     \
                    mma_fp16(acc[i][2*jp + 1], ah[i], bh + 2);                 \
                }                                                              \
            }                                                                  \
        }                                                                      \
    }

// ---------------------------------------------------------------------------
// 3) grouped GEMM1: h = silu(gather(xh) @ W1h + b1) -> fp16 h
// ---------------------------------------------------------------------------
__global__ void __launch_bounds__(256, 2)
gemm1_k(const float* __restrict__ eb1, const float* __restrict__ sb1) {
    extern __shared__ char smem[];
    const int t = blockIdx.y, n0 = blockIdx.x * 128, tid = threadIdx.x;
    int* s_tok = (int*)(smem + OFF_TOK);

    int e;
    const float* bias;
    if (t < 128) {
        e = t >> 4;
        int cnt = g_cnt[e];
        int lr0 = (t & 15) * 128;
        if (lr0 >= cnt) return;
        bias = eb1 + (size_t)e * IDIM;
        if (tid < 128) {
            int lr = lr0 + tid;
            s_tok[tid] = (lr < cnt) ? g_ptok[e * SEG + lr] : 0;
        }
    } else {
        e = 8; bias = sb1;
        if (tid < 128) s_tok[tid] = (t - 128) * 128 + tid;
    }
    __syncthreads();

    uint32_t smem_base = smem_u32(smem);
    const char* a_src = (const char*)(g_xh + (size_t)s_tok[tid >> 1] * CDIM)
                        + (tid & 1) * 32;
    const char* b_src = (const char*)(g_w1h
        + ((size_t)e * CDIM + (tid >> 3)) * IDIM + n0) + (tid & 7) * 32;

    GEMM_MAINLOOP(IDIM, CDIM / KC)

#pragma unroll
    for (int i = 0; i < 2; i++)
#pragma unroll
        for (int j = 0; j < 8; j++) {
            const int row0 = t * 128 + wm * 32 + i * 16 + g;
            const int col = n0 + wn * 64 + j * 8 + 2 * tt;
            float b0 = bias[col], b1 = bias[col + 1];
            float v0 = acc[i][j][0] + b0, v1 = acc[i][j][1] + b1;
            float v2 = acc[i][j][2] + b0, v3 = acc[i][j][3] + b1;
            v0 = v0 / (1.0f + __expf(-v0));
            v1 = v1 / (1.0f + __expf(-v1));
            v2 = v2 / (1.0f + __expf(-v2));
            v3 = v3 / (1.0f + __expf(-v3));
            uint32_t hlo, hhi;
            CVT2(hlo, v0, v1);
            CVT2(hhi, v2, v3);
            *(uint32_t*)((char*)g_h + ((size_t)row0 * IDIM + col) * 2) = hlo;
            *(uint32_t*)((char*)g_h + ((size_t)(row0 + 8) * IDIM + col) * 2) = hhi;
        }
}

// ---------------------------------------------------------------------------
// 4) grouped GEMM2: eo = h @ W2h + b2. grid (CDIM/128=8, 144). K=4096
// ---------------------------------------------------------------------------
__global__ void __launch_bounds__(256, 2)
gemm2_k(const float* __restrict__ eb2, const float* __restrict__ sb2) {
    extern __shared__ char smem[];
    const int t = blockIdx.y, n0 = blockIdx.x * 128, tid = threadIdx.x;

    int e;
    const float* bias;
    if (t < 128) {
        e = t >> 4;
        if ((t & 15) * 128 >= g_cnt[e]) return;
        bias = eb2 + (size_t)e * CDIM;
    } else {
        e = 8; bias = sb2;
    }
    __syncthreads();

    uint32_t smem_base = smem_u32(smem);
    const char* a_src = (const char*)(g_h + (size_t)(t * 128 + (tid >> 1)) * IDIM)
                        + (tid & 1) * 32;
    const char* b_src = (const char*)(g_w2h
        + ((size_t)e * IDIM + (tid >> 3)) * CDIM + n0) + (tid & 7) * 32;

    GEMM_MAINLOOP(CDIM, IDIM / KC)

#pragma unroll
    for (int i = 0; i < 2; i++)
#pragma unroll
        for (int j = 0; j < 8; j++) {
            const int row0 = t * 128 + wm * 32 + i * 16 + g;
            const int col = n0 + wn * 64 + j * 8 + 2 * tt;
            float b0 = bias[col], b1 = bias[col + 1];
            float2 lo, hi;
            lo.x = acc[i][j][0] + b0; lo.y = acc[i][j][1] + b1;
            hi.x = acc[i][j][2] + b0; hi.y = acc[i][j][3] + b1;
            *(float2*)(g_eo + (size_t)row0 * CDIM + col) = lo;
            *(float2*)(g_eo + (size_t)(row0 + 8) * CDIM + col) = hi;
        }
}

// ---------------------------------------------------------------------------
// 5) combine
// ---------------------------------------------------------------------------
__global__ void combine_kernel(float* __restrict__ out) {
    int gid = blockIdx.x * 256 + threadIdx.x;
    int n = gid >> 8, c4 = gid & 255;
    const float4* eo = (const float4*)g_eo;
    float4 o = eo[(size_t)(R_EXP + n) * (CDIM / 4) + c4];
    int   p0 = g_tpos[n * 2],     p1 = g_tpos[n * 2 + 1];
    float w0 = g_tw[n * 2],       w1 = g_tw[n * 2 + 1];
    float4 a = eo[(size_t)p0 * (CDIM / 4) + c4];
    float4 b = eo[(size_t)p1 * (CDIM / 4) + c4];
    o.x += w0 * a.x + w1 * b.x;
    o.y += w0 * a.y + w1 * b.y;
    o.z += w0 * a.z + w1 * b.z;
    o.w += w0 * a.w + w1 * b.w;
    ((float4*)out)[gid] = o;
}

// ---------------------------------------------------------------------------
extern "C" void kernel_launch(void* const* d_in, const int* in_sizes, int n_in,
                              void* d_out, int out_size) {
    const float* x   = (const float*)d_in[0];
    const float* rw1 = (const float*)d_in[1];
    const float* rb1 = (const float*)d_in[2];
    const float* rw2 = (const float*)d_in[3];
    const float* rb2 = (const float*)d_in[4];
    const float* ew1 = (const float*)d_in[5];
    const float* eb1 = (const float*)d_in[6];
    const float* ew2 = (const float*)d_in[7];
    const float* eb2 = (const float*)d_in[8];
    const float* sw1 = (const float*)d_in[9];
    const float* sb1 = (const float*)d_in[10];
    const float* sw2 = (const float*)d_in[11];
    const float* sb2 = (const float*)d_in[12];
    float* out = (float*)d_out;

    init_kernel<<<1, 32>>>();
    cvt_x_k<<<N_TOK * CDIM / 4 / 256, 256>>>(x);
    cvt_w_k<<<(int)(9 * WELEM / 4 / 256), 256>>>(ew1, sw1, 0);
    cvt_w_k<<<(int)(9 * WELEM / 4 / 256), 256>>>(ew2, sw2, 1);
    router_gemm<<<dim3(2, 16, RKS), 256>>>(x, rw1);
    sum_relu_kernel<<<N_TOK * RH / 4 / 256, 256>>>(rb1);
    route_kernel<<<256, 256>>>(rw2, rb2);
    gemm1_k<<<dim3(IDIM / 128, MT_TOT), 256, SMEM_TOTAL>>>(eb1, sb1);
    gemm2_k<<<dim3(CDIM / 128, MT_TOT), 256, SMEM_TOTAL>>>(eb2, sb2);
    combine_kernel<<<N_TOK * CDIM / 4 / 256, 256>>>(out);
}

// round 17
// speedup vs baseline: 2.3738x; 1.0029x over previous
#include <cuda_runtime.h>
#include <cuda_fp16.h>
#include <math.h>
#include <stdint.h>

// Problem dims
#define N_TOK 2048
#define CDIM  1024
#define RH    256
#define NE    8
#define IDIM  4096
#define SEG   2048
#define R_EXP (NE*SEG)          // 16384
#define R_TOT (R_EXP + N_TOK)   // 18432
#define MT_TOT (R_TOT/128)      // 144 row tiles
#define KC 64                   // K chunk (doubled: half the barriers)
#define RKS 8                   // router K-split
#define WELEM ((size_t)CDIM*IDIM)   // 2^22 elems per expert matrix

// SMEM layout (bytes). Per buffer: A[128][72]fp16 (144B rows: 128B data+16 pad),
// B[64][136]fp16 (272B rows: 256B data+16 pad)
#define OFF_TOK  64
#define OFF_A    1024
#define A_ROWB   144
#define A_ARR    (128*A_ROWB)           // 18432
#define OFF_B    (OFF_A + A_ARR)
#define B_ROWB   272
#define B_ARR    (64*B_ROWB)            // 17408
#define SBUF     (A_ARR + B_ARR)        // 35840 (one buffer)
#define SMEM_TOTAL (1024 + 2*SBUF)      // 72704  (x2 CTAs = 145408/SM)

// Scratch
__device__ __half g_xh[(size_t)N_TOK * CDIM];     // x in fp16
__device__ __half g_w1h[9 * WELEM];               // W1 (+shared) fp16
__device__ __half g_w2h[9 * WELEM];               // W2 (+shared) fp16
__device__ __half g_h [(size_t)R_TOT * IDIM];     // silu(x@W1+b1), fp16
__device__ float  g_eo[(size_t)R_TOT * CDIM];     // h@W2+b2 per row
__device__ float  g_y1p[(size_t)RKS * N_TOK * RH];
__device__ float  g_y1[N_TOK * RH];
__device__ int    g_cnt[NE];
__device__ int    g_ptok[R_EXP];
__device__ int    g_tpos[N_TOK * 2];
__device__ float  g_tw  [N_TOK * 2];

// ---------------------------------------------------------------------------
// helpers (all legal on base sm_103 target)
// ---------------------------------------------------------------------------
__device__ __forceinline__ void mma_fp16(float* d, const uint32_t* a, const uint32_t* b) {
    asm volatile(
        "mma.sync.aligned.m16n8k16.row.col.f32.f16.f16.f32 "
        "{%0,%1,%2,%3},{%4,%5,%6,%7},{%8,%9},{%0,%1,%2,%3};\n"
        : "+f"(d[0]), "+f"(d[1]), "+f"(d[2]), "+f"(d[3])
        : "r"(a[0]), "r"(a[1]), "r"(a[2]), "r"(a[3]), "r"(b[0]), "r"(b[1]));
}
#define LDMX4(r0,r1,r2,r3,addr) \
    asm volatile("ldmatrix.sync.aligned.m8n8.x4.shared.b16 {%0,%1,%2,%3}, [%4];" \
        : "=r"(r0),"=r"(r1),"=r"(r2),"=r"(r3) : "r"(addr))
#define LDMX4T(r0,r1,r2,r3,addr) \
    asm volatile("ldmatrix.sync.aligned.m8n8.x4.trans.shared.b16 {%0,%1,%2,%3}, [%4];" \
        : "=r"(r0),"=r"(r1),"=r"(r2),"=r"(r3) : "r"(addr))

// fp32 pair -> packed fp16x2 word (v0 in low half)
#define CVT2(hw, v0, v1) \
    asm("cvt.rn.f16x2.f32 %0, %1, %2;" : "=r"(hw) : "f"(v1), "f"(v0))

__device__ __forceinline__ uint32_t smem_u32(const void* p) {
    uint32_t a;
    asm("{ .reg .u64 t; cvta.to.shared.u64 t, %1; cvt.u32.u64 %0, t; }"
        : "=r"(a) : "l"(p));
    return a;
}
#define CP16(dst, src) asm volatile("cp.async.ca.shared.global [%0], [%1], 16;"::"r"(dst),"l"(src))
#define CP_COMMIT()    asm volatile("cp.async.commit_group;")
#define CP_WAIT0()     asm volatile("cp.async.wait_group 0;")

// ---------------------------------------------------------------------------
// 0) init counters
// ---------------------------------------------------------------------------
__global__ void init_kernel() {
    if (threadIdx.x < NE) g_cnt[threadIdx.x] = 0;
}

// ---------------------------------------------------------------------------
// 0b) fp32 -> fp16 converts. Destination selected IN DEVICE CODE (R15 lesson:
// passing a __device__ symbol from host passes the host shadow; ATS makes the
// bogus write land silently in host memory).
// ---------------------------------------------------------------------------
__global__ void cvt_x_k(const float* __restrict__ x) {
    size_t i = ((size_t)blockIdx.x * 256 + threadIdx.x) * 4;
    float4 v = *(const float4*)(x + i);
    uint32_t h0, h1;
    CVT2(h0, v.x, v.y);
    CVT2(h1, v.z, v.w);
    *(uint2*)(g_xh + i) = make_uint2(h0, h1);
}

__global__ void cvt_w_k(const float* __restrict__ ew,
                        const float* __restrict__ sw, int which) {
    size_t i = ((size_t)blockIdx.x * 256 + threadIdx.x) * 4;
    size_t e = i >> 22, off = i & (WELEM - 1);
    float4 v = (e < 8) ? *(const float4*)(ew + e * WELEM + off)
                       : *(const float4*)(sw + off);
    uint32_t h0, h1;
    CVT2(h0, v.x, v.y);
    CVT2(h1, v.z, v.w);
    __half* dst = which ? g_w2h : g_w1h;
    *(uint2*)(dst + i) = make_uint2(h0, h1);
}

// ---------------------------------------------------------------------------
// 1) router GEMM split-K=8 (deterministic partials)
// ---------------------------------------------------------------------------
__global__ void __launch_bounds__(256, 2)
router_gemm(const float* __restrict__ x, const float* __restrict__ rw1) {
    __shared__ float As[8][128];
    __shared__ float Bs[8][128];
    const int tid = threadIdx.x;
    const int m0 = blockIdx.y * 128;
    const int n0 = blockIdx.x * 128;
    const int ks = blockIdx.z * (CDIM / RKS);

    const int ar = tid >> 1, kh = (tid & 1) * 4;
    const int kb = tid >> 5, bn = (tid & 31) * 4;
    const float* arow = x + (size_t)(m0 + ar) * CDIM + ks;
    const float* bptr = rw1 + (size_t)(ks + kb) * RH + n0 + bn;
    const int tm = (tid >> 4) * 8, tn = (tid & 15) * 8;

    float acc[8][8];
#pragma unroll
    for (int i = 0; i < 8; i++)
#pragma unroll
        for (int j = 0; j < 8; j++) acc[i][j] = 0.0f;

    for (int k0 = 0; k0 < CDIM / RKS; k0 += 8) {
        float4 av = *(const float4*)(arow + k0 + kh);
        As[kh + 0][ar] = av.x; As[kh + 1][ar] = av.y;
        As[kh + 2][ar] = av.z; As[kh + 3][ar] = av.w;
        *(float4*)&Bs[kb][bn] = *(const float4*)(bptr + (size_t)k0 * RH);
        __syncthreads();
#pragma unroll
        for (int kk = 0; kk < 8; kk++) {
            float a[8], b[8];
#pragma unroll
            for (int i = 0; i < 8; i++) a[i] = As[kk][tm + i];
#pragma unroll
            for (int j = 0; j < 8; j++) b[j] = Bs[kk][tn + j];
#pragma unroll
            for (int i = 0; i < 8; i++)
#pragma unroll
                for (int j = 0; j < 8; j++) acc[i][j] += a[i] * b[j];
        }
        __syncthreads();
    }
#pragma unroll
    for (int i = 0; i < 8; i++) {
        float* dst = g_y1p + ((size_t)blockIdx.z * N_TOK + m0 + tm + i) * RH + n0 + tn;
#pragma unroll
        for (int j = 0; j < 8; j++) dst[j] = acc[i][j];
    }
}

// ---------------------------------------------------------------------------
// 1b) sum partials + rb1 + relu -> g_y1
// ---------------------------------------------------------------------------
__global__ void sum_relu_kernel(const float* __restrict__ rb1) {
    int i4 = blockIdx.x * 256 + threadIdx.x;
    const float4* p = (const float4*)g_y1p;
    float4 a = p[i4];
#pragma unroll
    for (int s = 1; s < RKS; s++) {
        float4 v = p[(size_t)s * (N_TOK * RH / 4) + i4];
        a.x += v.x; a.y += v.y; a.z += v.z; a.w += v.w;
    }
    float4 b = ((const float4*)rb1)[i4 & (RH / 4 - 1)];
    a.x = fmaxf(a.x + b.x, 0.0f);
    a.y = fmaxf(a.y + b.y, 0.0f);
    a.z = fmaxf(a.z + b.z, 0.0f);
    a.w = fmaxf(a.w + b.w, 0.0f);
    ((float4*)g_y1)[i4] = a;
}

// ---------------------------------------------------------------------------
// 2) routing (warp-per-token)
// ---------------------------------------------------------------------------
__global__ void route_kernel(const float* __restrict__ rw2,
                             const float* __restrict__ rb2) {
    __shared__ float s_w[RH * NE];
    __shared__ float s_b[NE];
    const int tid = threadIdx.x;
    for (int i = tid; i < RH * NE; i += 256) s_w[i] = rw2[i];
    if (tid < NE) s_b[tid] = rb2[tid];
    __syncthreads();

    const int n = blockIdx.x * 8 + (tid >> 5);
    const int lane = tid & 31;
    const float* y = g_y1 + (size_t)n * RH;

    float acc[NE];
#pragma unroll
    for (int e = 0; e < NE; e++) acc[e] = 0.0f;
#pragma unroll
    for (int cb = 0; cb < RH; cb += 32) {
        float v = y[cb + lane];
        const float* wrow = s_w + (cb + lane) * NE;
#pragma unroll
        for (int e = 0; e < NE; e++) acc[e] += v * wrow[e];
    }
#pragma unroll
    for (int off = 16; off > 0; off >>= 1)
#pragma unroll
        for (int e = 0; e < NE; e++)
            acc[e] += __shfl_down_sync(0xffffffff, acc[e], off);

    if (lane == 0) {
#pragma unroll
        for (int e = 0; e < NE; e++) acc[e] += s_b[e];
        float m = acc[0];
#pragma unroll
        for (int e = 1; e < NE; e++) m = fmaxf(m, acc[e]);
        float s = 0.0f, g[NE];
#pragma unroll
        for (int e = 0; e < NE; e++) { g[e] = expf(acc[e] - m); s += g[e]; }
        float inv = 1.0f / s;
#pragma unroll
        for (int e = 0; e < NE; e++) g[e] *= inv;

        int i1 = 0; float g1 = g[0];
#pragma unroll
        for (int e = 1; e < NE; e++) if (g[e] > g1) { g1 = g[e]; i1 = e; }
        int i2 = -1; float g2 = -1.0f;
#pragma unroll
        for (int e = 0; e < NE; e++)
            if (e != i1 && g[e] > g2) { g2 = g[e]; i2 = e; }

        float t  = expf((g2 - g1) * 0.5f);
        float d  = 1.0f / (1.0f + t);
        float w1 = d, w2 = t * d;

        int p1 = atomicAdd(&g_cnt[i1], 1);
        g_ptok[i1 * SEG + p1] = n;
        g_tpos[n * 2] = i1 * SEG + p1; g_tw[n * 2] = w1;
        int p2 = atomicAdd(&g_cnt[i2], 1);
        g_ptok[i2 * SEG + p2] = n;
        g_tpos[n * 2 + 1] = i2 * SEG + p2; g_tw[n * 2 + 1] = w2;
    }
}

// ---------------------------------------------------------------------------
// fp16 HMMA mainloop, KC=64, cp.async fills, 4 k-slabs per chunk.
// A fill: thread -> row tid>>1, 64B half (tid&1). B fill: k-row tid>>2,
// 64B quarter (tid&3).
// ---------------------------------------------------------------------------
#define FILLC(cc) do {                                                         \
    uint32_t _bo = (uint32_t)((cc) & 1) * SBUF;                                \
    const char* _a = a_src + (size_t)(cc) * (KC * 2);                          \
    CP16(a_dst + _bo,      _a);      CP16(a_dst + _bo + 16, _a + 16);          \
    CP16(a_dst + _bo + 32, _a + 32); CP16(a_dst + _bo + 48, _a + 48);          \
    const char* _b = b_src + (size_t)(cc) * bstep;                             \
    CP16(b_dst + _bo,      _b);      CP16(b_dst + _bo + 16, _b + 16);          \
    CP16(b_dst + _bo + 32, _b + 32); CP16(b_dst + _bo + 48, _b + 48);          \
    CP_COMMIT();                                                               \
} while (0)

#define GEMM_MAINLOOP(LDB, NCH)                                                \
    const int wid = tid >> 5, lane = tid & 31;                                 \
    const int wm = wid & 3, wn = wid >> 2;                                     \
    const int g = lane >> 2, tt = lane & 3;                                    \
    const size_t bstep = (size_t)KC * (LDB) * 2;                               \
    const uint32_t a_dst = smem_base + OFF_A                                   \
        + (uint32_t)((tid >> 1) * A_ROWB + (tid & 1) * 64);                    \
    const uint32_t b_dst = smem_base + OFF_B                                   \
        + (uint32_t)((tid >> 2) * B_ROWB + (tid & 3) * 64);                    \
    const uint32_t a_lm = smem_base + OFF_A +                                  \
        (uint32_t)((wm * 32 + (lane & 15)) * A_ROWB + (lane >> 4) * 16);       \
    const uint32_t b_lm = smem_base + OFF_B +                                  \
        (uint32_t)(((lane & 7) + ((lane >> 3) & 1) * 8) * B_ROWB              \
                   + (lane >> 4) * 16 + wn * 128);                             \
    float acc[2][8][4];                                                        \
    _Pragma("unroll")                                                          \
    for (int i = 0; i < 2; i++)                                                \
        _Pragma("unroll")                                                      \
        for (int j = 0; j < 8; j++)                                            \
            _Pragma("unroll")                                                  \
            for (int q = 0; q < 4; q++) acc[i][j][q] = 0.0f;                   \
    FILLC(0);                                                                  \
    for (int c = 0; c < (NCH); c++) {                                          \
        const uint32_t boff = (uint32_t)(c & 1) * SBUF;                        \
        CP_WAIT0();                                                            \
        __syncthreads();                                                       \
        if (c + 1 < (NCH)) { FILLC(c + 1); }                                   \
        _Pragma("unroll")                                                      \
        for (int slab = 0; slab < 4; slab++) {                                 \
            uint32_t ah[2][4];                                                 \
            _Pragma("unroll")                                                  \
            for (int i = 0; i < 2; i++) {                                      \
                uint32_t aa = a_lm + boff                                      \
                    + (uint32_t)(i * (16 * A_ROWB) + slab * 32);               \
                LDMX4(ah[i][0], ah[i][1], ah[i][2], ah[i][3], aa);             \
            }                                                                  \
            _Pragma("unroll")                                                  \
            for (int jp = 0; jp < 4; jp++) {                                   \
                uint32_t bh[4];                                                \
                uint32_t ba = b_lm + boff                                      \
                    + (uint32_t)(slab * (16 * B_ROWB) + jp * 32);              \
                LDMX4T(bh[0], bh[1], bh[2], bh[3], ba);                        \
                _Pragma("unroll")                                              \
                for (int i = 0; i < 2; i++) {                                  \
                    mma_fp16(acc[i][2*jp],     ah[i], bh);                     \
                    mma_fp16(acc[i][2*jp + 1], ah[i], bh + 2);                 \
                }                                                              \
            }                                                                  \
        }                                                                      \
    }

// ---------------------------------------------------------------------------
// 3) grouped GEMM1: h = silu(gather(xh) @ W1h + b1) -> fp16 h
// ---------------------------------------------------------------------------
__global__ void __launch_bounds__(256, 2)
gemm1_k(const float* __restrict__ eb1, const float* __restrict__ sb1) {
    extern __shared__ char smem[];
    const int t = blockIdx.y, n0 = blockIdx.x * 128, tid = threadIdx.x;
    int* s_tok = (int*)(smem + OFF_TOK);

    int e;
    const float* bias;
    if (t < 128) {
        e = t >> 4;
        int cnt = g_cnt[e];
        int lr0 = (t & 15) * 128;
        if (lr0 >= cnt) return;
        bias = eb1 + (size_t)e * IDIM;
        if (tid < 128) {
            int lr = lr0 + tid;
            s_tok[tid] = (lr < cnt) ? g_ptok[e * SEG + lr] : 0;
        }
    } else {
        e = 8; bias = sb1;
        if (tid < 128) s_tok[tid] = (t - 128) * 128 + tid;
    }
    __syncthreads();

    uint32_t smem_base = smem_u32(smem);
    const char* a_src = (const char*)(g_xh + (size_t)s_tok[tid >> 1] * CDIM)
                        + (tid & 1) * 64;
    const char* b_src = (const char*)(g_w1h
        + ((size_t)e * CDIM + (tid >> 2)) * IDIM + n0) + (tid & 3) * 64;

    GEMM_MAINLOOP(IDIM, CDIM / KC)

#pragma unroll
    for (int i = 0; i < 2; i++)
#pragma unroll
        for (int j = 0; j < 8; j++) {
            const int row0 = t * 128 + wm * 32 + i * 16 + g;
            const int col = n0 + wn * 64 + j * 8 + 2 * tt;
            float b0 = bias[col], b1 = bias[col + 1];
            float v0 = acc[i][j][0] + b0, v1 = acc[i][j][1] + b1;
            float v2 = acc[i][j][2] + b0, v3 = acc[i][j][3] + b1;
            v0 = v0 / (1.0f + __expf(-v0));
            v1 = v1 / (1.0f + __expf(-v1));
            v2 = v2 / (1.0f + __expf(-v2));
            v3 = v3 / (1.0f + __expf(-v3));
            uint32_t hlo, hhi;
            CVT2(hlo, v0, v1);
            CVT2(hhi, v2, v3);
            *(uint32_t*)((char*)g_h + ((size_t)row0 * IDIM + col) * 2) = hlo;
            *(uint32_t*)((char*)g_h + ((size_t)(row0 + 8) * IDIM + col) * 2) = hhi;
        }
}

// ---------------------------------------------------------------------------
// 4) grouped GEMM2: eo = h @ W2h + b2. grid (CDIM/128=8, 144). K=4096
// ---------------------------------------------------------------------------
__global__ void __launch_bounds__(256, 2)
gemm2_k(const float* __restrict__ eb2, const float* __restrict__ sb2) {
    extern __shared__ char smem[];
    const int t = blockIdx.y, n0 = blockIdx.x * 128, tid = threadIdx.x;

    int e;
    const float* bias;
    if (t < 128) {
        e = t >> 4;
        if ((t & 15) * 128 >= g_cnt[e]) return;
        bias = eb2 + (size_t)e * CDIM;
    } else {
        e = 8; bias = sb2;
    }
    __syncthreads();

    uint32_t smem_base = smem_u32(smem);
    const char* a_src = (const char*)(g_h + (size_t)(t * 128 + (tid >> 1)) * IDIM)
                        + (tid & 1) * 64;
    const char* b_src = (const char*)(g_w2h
        + ((size_t)e * IDIM + (tid >> 2)) * CDIM + n0) + (tid & 3) * 64;

    GEMM_MAINLOOP(CDIM, IDIM / KC)

#pragma unroll
    for (int i = 0; i < 2; i++)
#pragma unroll
        for (int j = 0; j < 8; j++) {
            const int row0 = t * 128 + wm * 32 + i * 16 + g;
            const int col = n0 + wn * 64 + j * 8 + 2 * tt;
            float b0 = bias[col], b1 = bias[col + 1];
            float2 lo, hi;
            lo.x = acc[i][j][0] + b0; lo.y = acc[i][j][1] + b1;
            hi.x = acc[i][j][2] + b0; hi.y = acc[i][j][3] + b1;
            *(float2*)(g_eo + (size_t)row0 * CDIM + col) = lo;
            *(float2*)(g_eo + (size_t)(row0 + 8) * CDIM + col) = hi;
        }
}

// ---------------------------------------------------------------------------
// 5) combine
// ---------------------------------------------------------------------------
__global__ void combine_kernel(float* __restrict__ out) {
    int gid = blockIdx.x * 256 + threadIdx.x;
    int n = gid >> 8, c4 = gid & 255;
    const float4* eo = (const float4*)g_eo;
    float4 o = eo[(size_t)(R_EXP + n) * (CDIM / 4) + c4];
    int   p0 = g_tpos[n * 2],     p1 = g_tpos[n * 2 + 1];
    float w0 = g_tw[n * 2],       w1 = g_tw[n * 2 + 1];
    float4 a = eo[(size_t)p0 * (CDIM / 4) + c4];
    float4 b = eo[(size_t)p1 * (CDIM / 4) + c4];
    o.x += w0 * a.x + w1 * b.x;
    o.y += w0 * a.y + w1 * b.y;
    o.z += w0 * a.z + w1 * b.z;
    o.w += w0 * a.w + w1 * b.w;
    ((float4*)out)[gid] = o;
}

// ---------------------------------------------------------------------------
extern "C" void kernel_launch(void* const* d_in, const int* in_sizes, int n_in,
                              void* d_out, int out_size) {
    const float* x   = (const float*)d_in[0];
    const float* rw1 = (const float*)d_in[1];
    const float* rb1 = (const float*)d_in[2];
    const float* rw2 = (const float*)d_in[3];
    const float* rb2 = (const float*)d_in[4];
    const float* ew1 = (const float*)d_in[5];
    const float* eb1 = (const float*)d_in[6];
    const float* ew2 = (const float*)d_in[7];
    const float* eb2 = (const float*)d_in[8];
    const float* sw1 = (const float*)d_in[9];
    const float* sb1 = (const float*)d_in[10];
    const float* sw2 = (const float*)d_in[11];
    const float* sb2 = (const float*)d_in[12];
    float* out = (float*)d_out;

    static bool attr_done = false;
    if (!attr_done) {
        cudaFuncSetAttribute(gemm1_k, cudaFuncAttributeMaxDynamicSharedMemorySize, SMEM_TOTAL);
        cudaFuncSetAttribute(gemm2_k, cudaFuncAttributeMaxDynamicSharedMemorySize, SMEM_TOTAL);
        attr_done = true;
    }

    init_kernel<<<1, 32>>>();
    cvt_x_k<<<N_TOK * CDIM / 4 / 256, 256>>>(x);
    cvt_w_k<<<(int)(9 * WELEM / 4 / 256), 256>>>(ew1, sw1, 0);
    cvt_w_k<<<(int)(9 * WELEM / 4 / 256), 256>>>(ew2, sw2, 1);
    router_gemm<<<dim3(2, 16, RKS), 256>>>(x, rw1);
    sum_relu_kernel<<<N_TOK * RH / 4 / 256, 256>>>(rb1);
    route_kernel<<<256, 256>>>(rw2, rb2);
    gemm1_k<<<dim3(IDIM / 128, MT_TOT), 256, SMEM_TOTAL>>>(eb1, sb1);
    gemm2_k<<<dim3(CDIM / 128, MT_TOT), 256, SMEM_TOTAL>>>(eb2, sb2);
    combine_kernel<<<N_TOK * CDIM / 4 / 256, 256>>>(out);
}